// round 14
// baseline (speedup 1.0000x reference)
#include <cuda_runtime.h>
#include <math.h>

// Problem constants
#define BB 16
#define PP 12
#define QQ 12
#define NN 1024
#define DD 64
#define HH 32
#define NZCAP 64
#define MPRE (BB*PP*NN)      // 196608 rows for precompute
#define MSTEP (BB*NN)        // 16384 rows per step
#define NBLK 128             // persistent loop grid size

// ---------------- scratch (device globals; no runtime allocation) ----------
__device__ float g_se[NN*HH];
__device__ float g_te[BB*24*HH];
__device__ float g_x [MPRE*64];      // input embedding (b,t,n,64)   id 0
__device__ float g_px1[MPRE*64];     // x Chebyshev terms            id 1
__device__ float g_px2[MPRE*64];     //                              id 2
__device__ float g_px3[MPRE*64];     //                              id 3
__device__ float g_Gx[(size_t)MPRE*128]; // precomputed x-part of gates
__device__ float g_Cx[MPRE*64];          // precomputed x-part of candidate
__device__ float g_h  [MSTEP*64];    // hidden state                 id 4
__device__ float g_ph1[MSTEP*64];    // per-step diffusion panels    id 5
__device__ float g_ph2[MSTEP*64];    //                              id 6
__device__ float g_ph3[MSTEP*64];    //                              id 7
__device__ float g_prh[MSTEP*64];    // r*h                          id 8
__device__ float g_u  [MSTEP*64];    // update gate
__device__ int2  g_ell[NZCAP*NN];    // j-major ELL: [j*NN+m] = {col, val}
__device__ int   g_nnz[NN];
// per-group barriers, padded to 128B lines
__device__ unsigned g_barc[16*32];
__device__ volatile unsigned g_barg[16*32];

__device__ __forceinline__ float* panel(int id){
  switch(id){
    case 0: return g_x;   case 1: return g_px1;
    case 2: return g_px2; case 3: return g_px3;
    case 4: return g_h;   case 5: return g_ph1;
    case 6: return g_ph2; case 7: return g_ph3;
    default: return g_prh;
  }
}

// smem tile swizzle: row m, float4 part p -> physical float4 slot.
// Bijective; spreads row start banks over 8 groups (vs 4 unswizzled).
__device__ __forceinline__ int ph(int m, int p){
  return (2*m + p) ^ ((m>>1)&7);
}

// ---------------- tf32 helpers ---------------------------------------------
__device__ __forceinline__ unsigned to_tf32(float v){
  unsigned h;
  asm("cvt.rna.tf32.f32 %0, %1;" : "=r"(h) : "f"(v));
  return h;
}

__device__ __forceinline__ void mma8(float c[4], const unsigned a[4],
                                     const unsigned b[2]){
  asm volatile(
    "mma.sync.aligned.m16n8k8.row.col.f32.tf32.tf32.f32 "
    "{%0,%1,%2,%3}, {%4,%5,%6,%7}, {%8,%9}, {%0,%1,%2,%3};"
    : "+f"(c[0]), "+f"(c[1]), "+f"(c[2]), "+f"(c[3])
    : "r"(a[0]), "r"(a[1]), "r"(a[2]), "r"(a[3]), "r"(b[0]), "r"(b[1]));
}

// ---------------- per-group grid barrier (8 blocks per group) --------------
__device__ __forceinline__ void gbar_g(int g){
  __threadfence();
  __syncthreads();
  if (threadIdx.x == 0){
    unsigned gen = g_barg[g*32];
    if (atomicAdd(&g_barc[g*32], 1u) == 7u){
      g_barc[g*32] = 0;
      __threadfence();
      g_barg[g*32] = gen + 1u;
    } else {
      while (g_barg[g*32] == gen) __nanosleep(32);
    }
  }
  __syncthreads();
}

// ---------------- small embeddings: se (N,32) and te (B,24,32) -------------
__global__ void k_small(const float* __restrict__ SE,
                        const float* __restrict__ Wse1, const float* __restrict__ bse1,
                        const float* __restrict__ Wse2, const float* __restrict__ bse2,
                        const float* __restrict__ Wte1, const float* __restrict__ bte1,
                        const float* __restrict__ Wte2, const float* __restrict__ bte2,
                        const int* __restrict__ TE){
  int tid = threadIdx.x;
  if (blockIdx.x < 4){
    int n = blockIdx.x*256 + tid;
    float in[32], hid[32];
    #pragma unroll
    for (int k=0;k<32;k++) in[k] = SE[n*32+k];
    #pragma unroll
    for (int j=0;j<32;j++){
      float a = bse1[j];
      #pragma unroll
      for (int k=0;k<32;k++) a = fmaf(in[k], Wse1[k*32+j], a);
      hid[j] = fmaxf(a, 0.f);
    }
    #pragma unroll
    for (int j=0;j<32;j++){
      float a = bse2[j];
      #pragma unroll
      for (int k=0;k<32;k++) a = fmaf(hid[k], Wse2[k*32+j], a);
      g_se[n*32+j] = a;
    }
  } else {
    int i = (blockIdx.x-4)*256 + tid;      // (b,t) flat, t in [0,24)
    if (i < BB*24){
      int day = TE[i*2+0], tod = TE[i*2+1];
      float hid[32];
      #pragma unroll
      for (int j=0;j<32;j++)
        hid[j] = fmaxf(Wte1[day*32+j] + Wte1[(7+tod)*32+j] + bte1[j], 0.f);
      #pragma unroll
      for (int j=0;j<32;j++){
        float a = bte2[j];
        #pragma unroll
        for (int k=0;k<32;k++) a = fmaf(hid[k], Wte2[k*32+j], a);
        g_te[i*32+j] = a;
      }
    }
  }
}

// ---------------- ELL extraction of L_s (j-major, coalesced consumers) -----
__global__ void k_csr(const float* __restrict__ Ls){
  int w = (blockIdx.x*blockDim.x + threadIdx.x) >> 5;
  int lane = threadIdx.x & 31;
  if (w >= NN) return;
  const float* row = Ls + (size_t)w*NN;
  int cnt = 0;
  for (int c0=0;c0<NN;c0+=32){
    float v = row[c0+lane];
    unsigned msk = __ballot_sync(0xffffffffu, v != 0.f);
    if (v != 0.f){
      int pos = cnt + __popc(msk & ((1u<<lane)-1u));
      if (pos < NZCAP) g_ell[pos*NN + w] = make_int2(c0+lane, __float_as_int(v));
    }
    cnt += __popc(msk);
  }
  int nz = cnt < NZCAP ? cnt : NZCAP;
  for (int j = nz + lane; j < NZCAP; j += 32)
    g_ell[j*NN + w] = make_int2(0, 0);
  if (lane==0) g_nnz[w] = nz;
}

// ---------------- input embedding + ZC conv + STE add, writes g_x ----------
__global__ void __launch_bounds__(256) k_embed(const float* __restrict__ X,
                        const float* __restrict__ ZC,
                        const float* __restrict__ Wconv, const float* __restrict__ bconv,
                        const float* __restrict__ W1, const float* __restrict__ b1,
                        const float* __restrict__ W2, const float* __restrict__ b2){
  __shared__ float sWc[98*32];
  __shared__ float sW2[64*32];
  __shared__ float sW1[64], sb1[64], sb2[32], sbc[32];
  __shared__ float srow[8][4][100];
  __shared__ float shid[8][4][64];
  int tid = threadIdx.x;
  for (int i=tid;i<98*32;i+=256) sWc[i]=Wconv[i];
  for (int i=tid;i<64*32;i+=256) sW2[i]=W2[i];
  if (tid<64){ sW1[tid]=W1[tid]; sb1[tid]=b1[tid]; }
  if (tid<32){ sb2[tid]=b2[tid]; sbc[tid]=bconv[tid]; }
  __syncthreads();
  int warp = tid>>5, lane = tid&31;
  int r0 = (blockIdx.x*8 + warp)*4;
  #pragma unroll
  for (int rr=0; rr<4; rr++){
    int row = r0 + rr;
    const float2* z = (const float2*)(ZC + (size_t)row*98);
    for (int i=lane;i<49;i+=32) *(float2*)&srow[warp][rr][2*i] = z[i];
    float xv = X[row];
    shid[warp][rr][lane]    = fmaxf(fmaf(xv, sW1[lane],    sb1[lane]),    0.f);
    shid[warp][rr][lane+32] = fmaxf(fmaf(xv, sW1[lane+32], sb1[lane+32]), 0.f);
  }
  __syncwarp();
  float zacc[4], e[4];
  #pragma unroll
  for (int rr=0;rr<4;rr++){ zacc[rr]=sbc[lane]; e[rr]=sb2[lane]; }
  #pragma unroll 2
  for (int i=0;i<98;i++){
    float w = sWc[i*32+lane];
    #pragma unroll
    for (int rr=0;rr<4;rr++) zacc[rr] = fmaf(srow[warp][rr][i], w, zacc[rr]);
  }
  #pragma unroll 2
  for (int k=0;k<64;k++){
    float w2 = sW2[k*32+lane];
    #pragma unroll
    for (int rr=0;rr<4;rr++) e[rr] = fmaf(shid[warp][rr][k], w2, e[rr]);
  }
  #pragma unroll
  for (int rr=0;rr<4;rr++){
    int row = r0 + rr;
    int b = row/(PP*NN); int pn = row%(PP*NN); int p = pn>>10; int n = pn&1023;
    float ste = g_se[n*32+lane] + g_te[(b*24+p)*32+lane];
    g_x[(size_t)row*64 + lane]      = e[rr] + ste;
    g_x[(size_t)row*64 + 32 + lane] = fmaxf(zacc[rr], 0.f);
  }
}

// ---------------- zero hidden state + barrier init -------------------------
__global__ void k_zeroh(){
  int i0 = blockIdx.x*blockDim.x + threadIdx.x;
  if (i0 < 16*32){ g_barc[i0] = 0; g_barg[i0] = 0; }
  for (int i = i0; i < MSTEP*64; i += gridDim.x*blockDim.x)
    g_h[i] = 0.f;
}

// ---------------- ELL gather: 8 cols for one row from swizzled tile --------
__device__ __forceinline__ void gather8(const float4* __restrict__ s,
                                        int m, int nnz, int wm,
                                        float4 &o0, float4 &o1){
  float4 a0 = make_float4(0.f,0.f,0.f,0.f), a1 = a0;
  float4 b0 = a0, b1 = a0;
  for (int j=0; j<wm; j+=2){
    if (j < nnz){
      int2 e = g_ell[j*NN + m];
      float v = __int_as_float(e.y);
      float4 f0 = s[ph(e.x,0)], f1 = s[ph(e.x,1)];
      a0.x=fmaf(v,f0.x,a0.x); a0.y=fmaf(v,f0.y,a0.y);
      a0.z=fmaf(v,f0.z,a0.z); a0.w=fmaf(v,f0.w,a0.w);
      a1.x=fmaf(v,f1.x,a1.x); a1.y=fmaf(v,f1.y,a1.y);
      a1.z=fmaf(v,f1.z,a1.z); a1.w=fmaf(v,f1.w,a1.w);
    }
    if (j+1 < nnz){
      int2 e = g_ell[(j+1)*NN + m];
      float v = __int_as_float(e.y);
      float4 f0 = s[ph(e.x,0)], f1 = s[ph(e.x,1)];
      b0.x=fmaf(v,f0.x,b0.x); b0.y=fmaf(v,f0.y,b0.y);
      b0.z=fmaf(v,f0.z,b0.z); b0.w=fmaf(v,f0.w,b0.w);
      b1.x=fmaf(v,f1.x,b1.x); b1.y=fmaf(v,f1.y,b1.y);
      b1.z=fmaf(v,f1.z,b1.z); b1.w=fmaf(v,f1.w,b1.w);
    }
  }
  o0 = make_float4(a0.x+b0.x, a0.y+b0.y, a0.z+b0.z, a0.w+b0.w);
  o1 = make_float4(a1.x+b1.x, a1.y+b1.y, a1.z+b1.z, a1.w+b1.w);
}

// ---------------- standalone fused Chebyshev (precompute path) -------------
__global__ void __launch_bounds__(1024) k_cheb3(int sid, int d1, int d2, int d3){
  __shared__ float4 s[2048];            // 1024 rows x 8 cols = 32KB (swizzled)
  const float* src = panel(sid);
  float* o1 = panel(d1);
  float* o2 = panel(d2);
  float* o3 = panel(d3);
  int g  = blockIdx.x >> 3;
  int c0 = (blockIdx.x & 7) * 8;
  int m  = threadIdx.x;
  size_t off = (size_t)(g*1024 + m)*64 + c0;
  int nnz = g_nnz[m];
  int wm = nnz;
  #pragma unroll
  for (int o=16;o;o>>=1) wm = max(wm, __shfl_xor_sync(0xffffffffu, wm, o));

  float4 r0a = *(const float4*)(src + off);
  float4 r0b = *(const float4*)(src + off + 4);
  s[ph(m,0)] = r0a; s[ph(m,1)] = r0b;
  __syncthreads();
  float4 r1a, r1b;
  gather8(s, m, nnz, wm, r1a, r1b);
  __syncthreads();
  s[ph(m,0)] = r1a; s[ph(m,1)] = r1b;
  *(float4*)(o1 + off)     = r1a;
  *(float4*)(o1 + off + 4) = r1b;
  __syncthreads();
  float4 ta, tb;
  gather8(s, m, nnz, wm, ta, tb);
  float4 r2a = make_float4(2.f*ta.x - r0a.x, 2.f*ta.y - r0a.y,
                           2.f*ta.z - r0a.z, 2.f*ta.w - r0a.w);
  float4 r2b = make_float4(2.f*tb.x - r0b.x, 2.f*tb.y - r0b.y,
                           2.f*tb.z - r0b.z, 2.f*tb.w - r0b.w);
  __syncthreads();
  s[ph(m,0)] = r2a; s[ph(m,1)] = r2b;
  *(float4*)(o2 + off)     = r2a;
  *(float4*)(o2 + off + 4) = r2b;
  __syncthreads();
  gather8(s, m, nnz, wm, ta, tb);
  float4 r3a = make_float4(2.f*ta.x - r1a.x, 2.f*ta.y - r1a.y,
                           2.f*ta.z - r1a.z, 2.f*ta.w - r1a.w);
  float4 r3b = make_float4(2.f*tb.x - r1b.x, 2.f*tb.y - r1b.y,
                           2.f*tb.z - r1b.z, 2.f*tb.w - r1b.w);
  *(float4*)(o3 + off)     = r3a;
  *(float4*)(o3 + off + 4) = r3b;
}

// ---------------- standalone tf32 MMA GEMM (precompute path, EPI 2) --------
template<int BN, int EPI>
__global__ void __launch_bounds__(2*BN) k_mma(int p0, int p1, int p2, int p3,
                        const float* __restrict__ W1, const float* __restrict__ W2,
                        int woff, const float* __restrict__ bias, int t){
  constexpr int NT = 2*BN;
  constexpr int LDW1 = (BN==64) ? 64 : 128;
  __shared__ unsigned sA[2][16][132];
  __shared__ unsigned sB[2][16][BN+4];
  int tid = threadIdx.x;
  int warp = tid>>5, lane = tid&31;
  int wm = (warp & 1)*64;
  int wn = (warp >> 1)*32;
  int m0 = blockIdx.x*128;

  float c[4][4][4];
  #pragma unroll
  for (int i=0;i<4;i++)
    #pragma unroll
    for (int j=0;j<4;j++)
      #pragma unroll
      for (int e=0;e<4;e++) c[i][j][e] = 0.f;

  const float* panels[4] = { panel(p0)+(size_t)m0*64, panel(p1)+(size_t)m0*64,
                             panel(p2)+(size_t)m0*64, panel(p3)+(size_t)m0*64 };

  auto load_chunk = [&](int cn, int bf){
    int kt = cn>>2, kc = (cn&3)*16;
    const float* Ap = panels[kt];
    for (int i=tid; i<512; i+=NT){
      int m = i>>2, q = i&3;
      float4 v = *(const float4*)(Ap + (size_t)m*64 + kc + q*4);
      sA[bf][q*4+0][m]=to_tf32(v.x);
      sA[bf][q*4+1][m]=to_tf32(v.y);
      sA[bf][q*4+2][m]=to_tf32(v.z);
      sA[bf][q*4+3][m]=to_tf32(v.w);
    }
    for (int i=tid; i<16*BN; i+=NT){
      int kr = i/BN, j = i%BN;
      int wrow = kt*128 + woff + kc + kr;
      float wv = (j < LDW1) ? W1[(size_t)wrow*LDW1 + j]
                            : W2[(size_t)wrow*64 + (j-LDW1)];
      sB[bf][kr][j]=to_tf32(wv);
    }
  };

  load_chunk(0, 0);
  __syncthreads();
  for (int cn=0; cn<16; cn++){
    int bf = cn & 1;
    if (cn+1 < 16) load_chunk(cn+1, bf^1);
    #pragma unroll
    for (int k8=0; k8<16; k8+=8){
      int bk = k8 + (lane&3);
      int bn = wn + (lane>>2);
      unsigned bh[4][2];
      #pragma unroll
      for (int j=0;j<4;j++){
        bh[j][0]=sB[bf][bk][bn+j*8]; bh[j][1]=sB[bf][bk+4][bn+j*8];
      }
      int ac = k8 + (lane&3);
      #pragma unroll
      for (int i=0;i<4;i++){
        int ar = wm + i*16 + (lane>>2);
        unsigned ah[4];
        ah[0]=sA[bf][ac][ar];   ah[1]=sA[bf][ac][ar+8];
        ah[2]=sA[bf][ac+4][ar]; ah[3]=sA[bf][ac+4][ar+8];
        #pragma unroll
        for (int j=0;j<4;j++) mma8(c[i][j], ah, bh[j]);
      }
    }
    __syncthreads();
  }

  #pragma unroll
  for (int i=0;i<4;i++){
    #pragma unroll
    for (int j=0;j<4;j++){
      #pragma unroll
      for (int e=0;e<4;e++){
        int r = (lane>>2) + ((e>=2) ? 8 : 0);
        int col = wn + j*8 + (lane&3)*2 + (e&1);
        size_t row = m0 + wm + i*16 + r;
        float v = c[i][j][e];
        if (EPI==2){
          if (col < 128) g_Gx[row*128 + col] = v;
          else           g_Cx[row*64 + (col-128)] = v;
        }
      }
    }
  }
}

// ============================================================================
// Persistent 12-step loop kernel: grid NBLK x 512. Block bx -> group g=bx>>3,
// sub=bx&7. All inter-block deps are intra-group; per-group 8-block barriers.
// Mutable panel traffic via __ldcg/__stcg (L2 = coherence point).
// ============================================================================
__device__ __forceinline__ void cheb_phase(char* smemraw, int sid,
                                           int d1, int d2, int d3){
  float4* s = (float4*)smemraw;
  const float* src = panel(sid);
  float* o1 = panel(d1);
  float* o2 = panel(d2);
  float* o3 = panel(d3);
  int g  = blockIdx.x >> 3;
  int c0 = (blockIdx.x & 7) * 8;
  int tid = threadIdx.x;
  float4 r0[2][2], r1[2][2], r2[2][2];
  int nz[2], wm[2];
  size_t off[2];
  #pragma unroll
  for (int rr=0; rr<2; rr++){
    int m = tid + rr*512;
    off[rr] = (size_t)(g*1024 + m)*64 + c0;
    r0[rr][0] = __ldcg((const float4*)(src + off[rr]));
    r0[rr][1] = __ldcg((const float4*)(src + off[rr] + 4));
    s[ph(m,0)] = r0[rr][0]; s[ph(m,1)] = r0[rr][1];
    nz[rr] = g_nnz[m];
    int w = nz[rr];
    #pragma unroll
    for (int o=16;o;o>>=1) w = max(w, __shfl_xor_sync(0xffffffffu, w, o));
    wm[rr] = w;
  }
  __syncthreads();
  #pragma unroll
  for (int rr=0; rr<2; rr++)
    gather8(s, tid+rr*512, nz[rr], wm[rr], r1[rr][0], r1[rr][1]);
  __syncthreads();
  #pragma unroll
  for (int rr=0; rr<2; rr++){
    int m = tid + rr*512;
    s[ph(m,0)] = r1[rr][0]; s[ph(m,1)] = r1[rr][1];
    __stcg((float4*)(o1 + off[rr]),     r1[rr][0]);
    __stcg((float4*)(o1 + off[rr] + 4), r1[rr][1]);
  }
  __syncthreads();
  #pragma unroll
  for (int rr=0; rr<2; rr++){
    float4 ta, tb;
    gather8(s, tid+rr*512, nz[rr], wm[rr], ta, tb);
    r2[rr][0] = make_float4(2.f*ta.x - r0[rr][0].x, 2.f*ta.y - r0[rr][0].y,
                            2.f*ta.z - r0[rr][0].z, 2.f*ta.w - r0[rr][0].w);
    r2[rr][1] = make_float4(2.f*tb.x - r0[rr][1].x, 2.f*tb.y - r0[rr][1].y,
                            2.f*tb.z - r0[rr][1].z, 2.f*tb.w - r0[rr][1].w);
  }
  __syncthreads();
  #pragma unroll
  for (int rr=0; rr<2; rr++){
    int m = tid + rr*512;
    s[ph(m,0)] = r2[rr][0]; s[ph(m,1)] = r2[rr][1];
    __stcg((float4*)(o2 + off[rr]),     r2[rr][0]);
    __stcg((float4*)(o2 + off[rr] + 4), r2[rr][1]);
  }
  __syncthreads();
  #pragma unroll
  for (int rr=0; rr<2; rr++){
    float4 ta, tb;
    gather8(s, tid+rr*512, nz[rr], wm[rr], ta, tb);
    float4 r3a = make_float4(2.f*ta.x - r1[rr][0].x, 2.f*ta.y - r1[rr][0].y,
                             2.f*ta.z - r1[rr][0].z, 2.f*ta.w - r1[rr][0].w);
    float4 r3b = make_float4(2.f*ta.x*0.f + 2.f*tb.x - r1[rr][1].x,
                             2.f*tb.y - r1[rr][1].y,
                             2.f*tb.z - r1[rr][1].z, 2.f*tb.w - r1[rr][1].w);
    __stcg((float4*)(o3 + off[rr]),     r3a);
    __stcg((float4*)(o3 + off[rr] + 4), r3b);
  }
}

// MMA phase: block = 128-row M-tile, 16 warps, warp-tile 32x16.
template<int BN, int EPI>
__device__ __forceinline__ void mma_phase(char* smemraw,
    int p0, int p1, int p2, int p3,
    const float* __restrict__ W1, int woff,
    const float* __restrict__ bias, int t){
  constexpr int LDW1 = (BN==64) ? 64 : 128;
  constexpr int JN = BN/16;                  // 8 or 4
  constexpr int NJ = (4*JN + 15)/16;         // 2 or 1 jobs per warp
  unsigned (*sA)[132] = (unsigned(*)[132])smemraw;           // [2*16][132]
  unsigned (*sB)[132] = (unsigned(*)[132])(smemraw + 16896); // [2*16][132]
  int tid = threadIdx.x, warp = tid>>5, lane = tid&31;
  int m0 = blockIdx.x*128;

  float c[NJ][2][2][4];
  #pragma unroll
  for (int jw=0;jw<NJ;jw++)
    #pragma unroll
    for (int mi=0;mi<2;mi++)
      #pragma unroll
      for (int ni=0;ni<2;ni++)
        #pragma unroll
        for (int e=0;e<4;e++) c[jw][mi][ni][e] = 0.f;

  const float* panels[4] = { panel(p0)+(size_t)m0*64, panel(p1)+(size_t)m0*64,
                             panel(p2)+(size_t)m0*64, panel(p3)+(size_t)m0*64 };

  auto load_chunk = [&](int cn, int bf){
    int kt = cn>>2, kc = (cn&3)*16;
    const float* Ap = panels[kt];
    {
      int m = tid>>2, q = tid&3;
      float4 v = __ldcg((const float4*)(Ap + (size_t)m*64 + kc + q*4));
      sA[bf*16+q*4+0][m]=to_tf32(v.x);
      sA[bf*16+q*4+1][m]=to_tf32(v.y);
      sA[bf*16+q*4+2][m]=to_tf32(v.z);
      sA[bf*16+q*4+3][m]=to_tf32(v.w);
    }
    if (tid < 4*BN){
      int kr = tid/(BN/4), n4 = tid%(BN/4);
      int wrow = kt*128 + woff + kc + kr;
      float4 wv = *(const float4*)(W1 + (size_t)wrow*LDW1 + n4*4);
      sB[bf*16+kr][n4*4+0]=to_tf32(wv.x);
      sB[bf*16+kr][n4*4+1]=to_tf32(wv.y);
      sB[bf*16+kr][n4*4+2]=to_tf32(wv.z);
      sB[bf*16+kr][n4*4+3]=to_tf32(wv.w);
    }
  };

  load_chunk(0, 0);
  __syncthreads();
  for (int cn=0; cn<16; cn++){
    int bf = cn & 1;
    if (cn+1 < 16) load_chunk(cn+1, bf^1);
    #pragma unroll
    for (int k8=0; k8<16; k8+=8){
      int ac = k8 + (lane&3);
      #pragma unroll
      for (int jw=0; jw<NJ; jw++){
        int job = warp + jw*16;
        int jm = job / JN, jn = job % JN;
        unsigned bh[2][2];
        #pragma unroll
        for (int ni=0; ni<2; ni++){
          int bc = jn*16 + ni*8 + (lane>>2);
          bh[ni][0]=sB[bf*16+ac][bc];
          bh[ni][1]=sB[bf*16+ac+4][bc];
        }
        #pragma unroll
        for (int mi=0; mi<2; mi++){
          int ar = jm*32 + mi*16 + (lane>>2);
          unsigned ah[4];
          ah[0]=sA[bf*16+ac][ar];   ah[1]=sA[bf*16+ac][ar+8];
          ah[2]=sA[bf*16+ac+4][ar]; ah[3]=sA[bf*16+ac+4][ar+8];
          #pragma unroll
          for (int ni=0; ni<2; ni++) mma8(c[jw][mi][ni], ah, bh[ni]);
        }
      }
    }
    __syncthreads();
  }

  #pragma unroll
  for (int jw=0; jw<NJ; jw++){
    int job = warp + jw*16;
    int jm = job / JN, jn = job % JN;
    #pragma unroll
    for (int mi=0; mi<2; mi++){
      #pragma unroll
      for (int ni=0; ni<2; ni++){
        #pragma unroll
        for (int e=0; e<4; e++){
          int r = (lane>>2) + ((e>=2) ? 8 : 0);
          int col = jn*16 + ni*8 + (lane&3)*2 + (e&1);
          size_t row = m0 + jm*32 + mi*16 + r;
          float v = c[jw][mi][ni][e];
          size_t xrow = ((row>>10)*12 + t)*1024 + (row&1023);
          if (EPI==0){
            v += g_Gx[xrow*128 + col] + bias[col];
            float s = 1.f/(1.f+expf(-v));
            if (col < 64)
              __stcg(&g_prh[row*64 + col], s * __ldcg(&g_h[row*64 + col]));
            else
              __stcg(&g_u[row*64 + (col-64)], s);
          } else {
            v += g_Cx[xrow*64 + col] + bias[col];
            float cc = tanhf(v);
            float u = __ldcg(&g_u[row*64 + col]);
            float h = __ldcg(&g_h[row*64 + col]);
            __stcg(&g_h[row*64 + col], u*h + (1.f-u)*cc);
          }
        }
      }
    }
  }
}

__global__ void __launch_bounds__(512) k_loop(
    const float* __restrict__ Wg, const float* __restrict__ bg,
    const float* __restrict__ Wc, const float* __restrict__ bc){
  __shared__ __align__(16) char sm[33792];
  int g = blockIdx.x >> 3;
  for (int t=0; t<12; t++){
    cheb_phase(sm, 4, 5,6,7);
    gbar_g(g);
    mma_phase<128,0>(sm, 4,5,6,7, Wg, 64, bg, t);
    gbar_g(g);
    cheb_phase(sm, 8, 5,6,7);
    gbar_g(g);
    mma_phase<64,1>(sm, 8,5,6,7, Wc, 64, bc, t);
    gbar_g(g);
  }
}

// ---------------- output head ----------------------------------------------
__global__ void __launch_bounds__(256) k_out(const float* __restrict__ Wo1,
                        const float* __restrict__ bo1,
                        const float* __restrict__ Wo2, const float* __restrict__ bo2,
                        float* __restrict__ out){
  __shared__ float sW1[64*64];
  __shared__ float sW2[64*12];
  __shared__ float sb1[64], sb2[12];
  __shared__ float shrow[8][64];
  __shared__ float shid[8][64];
  int tid = threadIdx.x;
  for (int i=tid;i<64*64;i+=256) sW1[i]=Wo1[i];
  for (int i=tid;i<64*12;i+=256) sW2[i]=Wo2[i];
  if (tid<64) sb1[tid]=bo1[tid];
  if (tid<12) sb2[tid]=bo2[tid];
  __syncthreads();
  int warp = tid>>5, lane = tid&31;
  int row = blockIdx.x*8 + warp;            // < 16384 exactly
  shrow[warp][lane]    = g_h[(size_t)row*64 + lane];
  shrow[warp][lane+32] = g_h[(size_t)row*64 + lane + 32];
  __syncwarp();
  #pragma unroll
  for (int half=0; half<2; half++){
    int jj = lane + half*32;
    float a = sb1[jj];
    #pragma unroll
    for (int k=0;k<64;k++) a = fmaf(shrow[warp][k], sW1[k*64+jj], a);
    shid[warp][jj] = fmaxf(a, 0.f);
  }
  __syncwarp();
  if (lane < 12){
    float a = sb2[lane];
    #pragma unroll
    for (int k=0;k<64;k++) a = fmaf(shid[warp][k], sW2[k*12+lane], a);
    int b = row>>10, n = row&1023;
    out[(size_t)(b*12 + lane)*1024 + n] = a;
  }
}

// ---------------- host launcher --------------------------------------------
extern "C" void kernel_launch(void* const* d_in, const int* in_sizes, int n_in,
                              void* d_out, int out_size){
  const float* X     = (const float*)d_in[0];
  const float* ZC    = (const float*)d_in[1];
  const int*   TE    = (const int*)  d_in[2];
  const float* Ls    = (const float*)d_in[3];
  const float* SE    = (const float*)d_in[4];
  const float* Wse1  = (const float*)d_in[5];
  const float* bse1  = (const float*)d_in[6];
  const float* Wse2  = (const float*)d_in[7];
  const float* bse2  = (const float*)d_in[8];
  const float* Wte1  = (const float*)d_in[9];
  const float* bte1  = (const float*)d_in[10];
  const float* Wte2  = (const float*)d_in[11];
  const float* bte2  = (const float*)d_in[12];
  const float* Win1  = (const float*)d_in[13];
  const float* bin1  = (const float*)d_in[14];
  const float* Win2  = (const float*)d_in[15];
  const float* bin2  = (const float*)d_in[16];
  const float* Wconv = (const float*)d_in[17];
  const float* bconv = (const float*)d_in[18];
  const float* Wg    = (const float*)d_in[19];
  const float* bg    = (const float*)d_in[20];
  const float* Wc    = (const float*)d_in[21];
  const float* bc    = (const float*)d_in[22];
  const float* Wo1   = (const float*)d_in[23];
  const float* bo1   = (const float*)d_in[24];
  const float* Wo2   = (const float*)d_in[25];
  const float* bo2   = (const float*)d_in[26];
  float* out = (float*)d_out;

  k_zeroh<<<512,256>>>();
  k_small<<<6,256>>>(SE,Wse1,bse1,Wse2,bse2,Wte1,bte1,Wte2,bte2,TE);
  k_csr<<<32,1024>>>(Ls);
  k_embed<<<6144,256>>>(X,ZC,Wconv,bconv,Win1,bin1,Win2,bin2);

  // precompute: x Chebyshev terms + combined x-part GEMM (Gx | Cx)
  k_cheb3<<<192*8,1024>>>(0, 1,2,3);
  k_mma<192,2><<<1536,384>>>(0,1,2,3, Wg, Wc, 0, Wg, 0);

  // persistent 12-step DCGRU loop (per-group barriers)
  k_loop<<<NBLK,512>>>(Wg, bg, Wc, bc);

  k_out<<<2048,256>>>(Wo1,bo1,Wo2,bo2,out);
}

// round 15
// speedup vs baseline: 1.0765x; 1.0765x over previous
#include <cuda_runtime.h>
#include <math.h>

// Problem constants
#define BB 16
#define PP 12
#define QQ 12
#define NN 1024
#define DD 64
#define HH 32
#define NZCAP 64
#define MPRE (BB*PP*NN)      // 196608 rows for precompute
#define MSTEP (BB*NN)        // 16384 rows per step
#define NBLK 128             // persistent loop grid size

// ---------------- scratch (device globals; no runtime allocation) ----------
__device__ float g_se[NN*HH];
__device__ float g_te[BB*24*HH];
__device__ float g_x [MPRE*64];      // input embedding (b,t,n,64)   id 0
__device__ float g_px1[MPRE*64];     // x Chebyshev terms            id 1
__device__ float g_px2[MPRE*64];     //                              id 2
__device__ float g_px3[MPRE*64];     //                              id 3
__device__ float g_Gx[(size_t)MPRE*128]; // precomputed x-part of gates
__device__ float g_Cx[MPRE*64];          // precomputed x-part of candidate
__device__ float g_h  [MSTEP*64];    // hidden state                 id 4
__device__ float g_ph1[MSTEP*64];    // per-step diffusion panels    id 5
__device__ float g_ph2[MSTEP*64];    //                              id 6
__device__ float g_ph3[MSTEP*64];    //                              id 7
__device__ float g_prh[MSTEP*64];    // r*h                          id 8
__device__ float g_u  [MSTEP*64];    // update gate
__device__ int2  g_ell[NZCAP*NN];    // j-major ELL: [j*NN+m] = {col, val}
__device__ int   g_nnz[NN];
// per-group barriers, padded to 128B lines
__device__ unsigned g_barc[16*32];
__device__ volatile unsigned g_barg[16*32];

__device__ __forceinline__ float* panel(int id){
  switch(id){
    case 0: return g_x;   case 1: return g_px1;
    case 2: return g_px2; case 3: return g_px3;
    case 4: return g_h;   case 5: return g_ph1;
    case 6: return g_ph2; case 7: return g_ph3;
    default: return g_prh;
  }
}

// ---------------- tf32 helpers ---------------------------------------------
__device__ __forceinline__ unsigned to_tf32(float v){
  unsigned h;
  asm("cvt.rna.tf32.f32 %0, %1;" : "=r"(h) : "f"(v));
  return h;
}

__device__ __forceinline__ void mma8(float c[4], const unsigned a[4],
                                     const unsigned b[2]){
  asm volatile(
    "mma.sync.aligned.m16n8k8.row.col.f32.tf32.tf32.f32 "
    "{%0,%1,%2,%3}, {%4,%5,%6,%7}, {%8,%9}, {%0,%1,%2,%3};"
    : "+f"(c[0]), "+f"(c[1]), "+f"(c[2]), "+f"(c[3])
    : "r"(a[0]), "r"(a[1]), "r"(a[2]), "r"(a[3]), "r"(b[0]), "r"(b[1]));
}

// ---------------- per-group grid barrier (8 blocks per group) --------------
__device__ __forceinline__ void gbar_g(int g){
  __threadfence();
  __syncthreads();
  if (threadIdx.x == 0){
    unsigned gen = g_barg[g*32];
    if (atomicAdd(&g_barc[g*32], 1u) == 7u){
      g_barc[g*32] = 0;
      __threadfence();
      g_barg[g*32] = gen + 1u;
    } else {
      while (g_barg[g*32] == gen) __nanosleep(32);
    }
  }
  __syncthreads();
}

// ---------------- small embeddings: se (N,32) and te (B,24,32) -------------
__global__ void k_small(const float* __restrict__ SE,
                        const float* __restrict__ Wse1, const float* __restrict__ bse1,
                        const float* __restrict__ Wse2, const float* __restrict__ bse2,
                        const float* __restrict__ Wte1, const float* __restrict__ bte1,
                        const float* __restrict__ Wte2, const float* __restrict__ bte2,
                        const int* __restrict__ TE){
  int tid = threadIdx.x;
  if (blockIdx.x < 4){
    int n = blockIdx.x*256 + tid;
    float in[32], hid[32];
    #pragma unroll
    for (int k=0;k<32;k++) in[k] = SE[n*32+k];
    #pragma unroll
    for (int j=0;j<32;j++){
      float a = bse1[j];
      #pragma unroll
      for (int k=0;k<32;k++) a = fmaf(in[k], Wse1[k*32+j], a);
      hid[j] = fmaxf(a, 0.f);
    }
    #pragma unroll
    for (int j=0;j<32;j++){
      float a = bse2[j];
      #pragma unroll
      for (int k=0;k<32;k++) a = fmaf(hid[k], Wse2[k*32+j], a);
      g_se[n*32+j] = a;
    }
  } else {
    int i = (blockIdx.x-4)*256 + tid;      // (b,t) flat, t in [0,24)
    if (i < BB*24){
      int day = TE[i*2+0], tod = TE[i*2+1];
      float hid[32];
      #pragma unroll
      for (int j=0;j<32;j++)
        hid[j] = fmaxf(Wte1[day*32+j] + Wte1[(7+tod)*32+j] + bte1[j], 0.f);
      #pragma unroll
      for (int j=0;j<32;j++){
        float a = bte2[j];
        #pragma unroll
        for (int k=0;k<32;k++) a = fmaf(hid[k], Wte2[k*32+j], a);
        g_te[i*32+j] = a;
      }
    }
  }
}

// ---------------- ELL extraction of L_s (j-major, coalesced consumers) -----
__global__ void k_csr(const float* __restrict__ Ls){
  int w = (blockIdx.x*blockDim.x + threadIdx.x) >> 5;
  int lane = threadIdx.x & 31;
  if (w >= NN) return;
  const float* row = Ls + (size_t)w*NN;
  int cnt = 0;
  for (int c0=0;c0<NN;c0+=32){
    float v = row[c0+lane];
    unsigned msk = __ballot_sync(0xffffffffu, v != 0.f);
    if (v != 0.f){
      int pos = cnt + __popc(msk & ((1u<<lane)-1u));
      if (pos < NZCAP) g_ell[pos*NN + w] = make_int2(c0+lane, __float_as_int(v));
    }
    cnt += __popc(msk);
  }
  int nz = cnt < NZCAP ? cnt : NZCAP;
  for (int j = nz + lane; j < NZCAP; j += 32)
    g_ell[j*NN + w] = make_int2(0, 0);
  if (lane==0) g_nnz[w] = nz;
}

// ---------------- input embedding + ZC conv + STE add, writes g_x ----------
__global__ void __launch_bounds__(256) k_embed(const float* __restrict__ X,
                        const float* __restrict__ ZC,
                        const float* __restrict__ Wconv, const float* __restrict__ bconv,
                        const float* __restrict__ W1, const float* __restrict__ b1,
                        const float* __restrict__ W2, const float* __restrict__ b2){
  __shared__ float sWc[98*32];
  __shared__ float sW2[64*32];
  __shared__ float sW1[64], sb1[64], sb2[32], sbc[32];
  __shared__ float srow[8][4][100];
  __shared__ float shid[8][4][64];
  int tid = threadIdx.x;
  for (int i=tid;i<98*32;i+=256) sWc[i]=Wconv[i];
  for (int i=tid;i<64*32;i+=256) sW2[i]=W2[i];
  if (tid<64){ sW1[tid]=W1[tid]; sb1[tid]=b1[tid]; }
  if (tid<32){ sb2[tid]=b2[tid]; sbc[tid]=bconv[tid]; }
  __syncthreads();
  int warp = tid>>5, lane = tid&31;
  int r0 = (blockIdx.x*8 + warp)*4;
  #pragma unroll
  for (int rr=0; rr<4; rr++){
    int row = r0 + rr;
    const float2* z = (const float2*)(ZC + (size_t)row*98);
    for (int i=lane;i<49;i+=32) *(float2*)&srow[warp][rr][2*i] = z[i];
    float xv = X[row];
    shid[warp][rr][lane]    = fmaxf(fmaf(xv, sW1[lane],    sb1[lane]),    0.f);
    shid[warp][rr][lane+32] = fmaxf(fmaf(xv, sW1[lane+32], sb1[lane+32]), 0.f);
  }
  __syncwarp();
  float zacc[4], e[4];
  #pragma unroll
  for (int rr=0;rr<4;rr++){ zacc[rr]=sbc[lane]; e[rr]=sb2[lane]; }
  #pragma unroll 2
  for (int i=0;i<98;i++){
    float w = sWc[i*32+lane];
    #pragma unroll
    for (int rr=0;rr<4;rr++) zacc[rr] = fmaf(srow[warp][rr][i], w, zacc[rr]);
  }
  #pragma unroll 2
  for (int k=0;k<64;k++){
    float w2 = sW2[k*32+lane];
    #pragma unroll
    for (int rr=0;rr<4;rr++) e[rr] = fmaf(shid[warp][rr][k], w2, e[rr]);
  }
  #pragma unroll
  for (int rr=0;rr<4;rr++){
    int row = r0 + rr;
    int b = row/(PP*NN); int pn = row%(PP*NN); int p = pn>>10; int n = pn&1023;
    float ste = g_se[n*32+lane] + g_te[(b*24+p)*32+lane];
    g_x[(size_t)row*64 + lane]      = e[rr] + ste;
    g_x[(size_t)row*64 + 32 + lane] = fmaxf(zacc[rr], 0.f);
  }
}

// ---------------- zero hidden state + barrier init -------------------------
__global__ void k_zeroh(){
  int i0 = blockIdx.x*blockDim.x + threadIdx.x;
  if (i0 < 16*32){ g_barc[i0] = 0; g_barg[i0] = 0; }
  for (int i = i0; i < MSTEP*64; i += gridDim.x*blockDim.x)
    g_h[i] = 0.f;
}

// ---------------- ELL gather: 8 cols for one row from smem tile ------------
__device__ __forceinline__ void gather8(const float4* __restrict__ s,
                                        int m, int nnz, int wm,
                                        float4 &o0, float4 &o1){
  float4 a0 = make_float4(0.f,0.f,0.f,0.f), a1 = a0;
  float4 b0 = a0, b1 = a0;
  for (int j=0; j<wm; j+=2){
    if (j < nnz){
      int2 e = g_ell[j*NN + m];
      float v = __int_as_float(e.y);
      float4 f0 = s[e.x*2], f1 = s[e.x*2+1];
      a0.x=fmaf(v,f0.x,a0.x); a0.y=fmaf(v,f0.y,a0.y);
      a0.z=fmaf(v,f0.z,a0.z); a0.w=fmaf(v,f0.w,a0.w);
      a1.x=fmaf(v,f1.x,a1.x); a1.y=fmaf(v,f1.y,a1.y);
      a1.z=fmaf(v,f1.z,a1.z); a1.w=fmaf(v,f1.w,a1.w);
    }
    if (j+1 < nnz){
      int2 e = g_ell[(j+1)*NN + m];
      float v = __int_as_float(e.y);
      float4 f0 = s[e.x*2], f1 = s[e.x*2+1];
      b0.x=fmaf(v,f0.x,b0.x); b0.y=fmaf(v,f0.y,b0.y);
      b0.z=fmaf(v,f0.z,b0.z); b0.w=fmaf(v,f0.w,b0.w);
      b1.x=fmaf(v,f1.x,b1.x); b1.y=fmaf(v,f1.y,b1.y);
      b1.z=fmaf(v,f1.z,b1.z); b1.w=fmaf(v,f1.w,b1.w);
    }
  }
  o0 = make_float4(a0.x+b0.x, a0.y+b0.y, a0.z+b0.z, a0.w+b0.w);
  o1 = make_float4(a1.x+b1.x, a1.y+b1.y, a1.z+b1.z, a1.w+b1.w);
}

// ---------------- standalone fused Chebyshev (precompute path) -------------
__global__ void __launch_bounds__(1024) k_cheb3(int sid, int d1, int d2, int d3){
  __shared__ float4 s[2048];            // 1024 rows x 8 cols = 32KB
  const float* src = panel(sid);
  float* o1 = panel(d1);
  float* o2 = panel(d2);
  float* o3 = panel(d3);
  int g  = blockIdx.x >> 3;
  int c0 = (blockIdx.x & 7) * 8;
  int m  = threadIdx.x;
  size_t off = (size_t)(g*1024 + m)*64 + c0;
  int nnz = g_nnz[m];
  int wm = nnz;
  #pragma unroll
  for (int o=16;o;o>>=1) wm = max(wm, __shfl_xor_sync(0xffffffffu, wm, o));

  float4 r0a = *(const float4*)(src + off);
  float4 r0b = *(const float4*)(src + off + 4);
  s[2*m] = r0a; s[2*m+1] = r0b;
  __syncthreads();
  float4 r1a, r1b;
  gather8(s, m, nnz, wm, r1a, r1b);
  __syncthreads();
  s[2*m] = r1a; s[2*m+1] = r1b;
  *(float4*)(o1 + off)     = r1a;
  *(float4*)(o1 + off + 4) = r1b;
  __syncthreads();
  float4 ta, tb;
  gather8(s, m, nnz, wm, ta, tb);
  float4 r2a = make_float4(2.f*ta.x - r0a.x, 2.f*ta.y - r0a.y,
                           2.f*ta.z - r0a.z, 2.f*ta.w - r0a.w);
  float4 r2b = make_float4(2.f*tb.x - r0b.x, 2.f*tb.y - r0b.y,
                           2.f*tb.z - r0b.z, 2.f*tb.w - r0b.w);
  __syncthreads();
  s[2*m] = r2a; s[2*m+1] = r2b;
  *(float4*)(o2 + off)     = r2a;
  *(float4*)(o2 + off + 4) = r2b;
  __syncthreads();
  gather8(s, m, nnz, wm, ta, tb);
  float4 r3a = make_float4(2.f*ta.x - r1a.x, 2.f*ta.y - r1a.y,
                           2.f*ta.z - r1a.z, 2.f*ta.w - r1a.w);
  float4 r3b = make_float4(2.f*tb.x - r1b.x, 2.f*tb.y - r1b.y,
                           2.f*tb.z - r1b.z, 2.f*tb.w - r1b.w);
  *(float4*)(o3 + off)     = r3a;
  *(float4*)(o3 + off + 4) = r3b;
}

// ---------------- standalone tf32 MMA GEMM (precompute path, EPI 2) --------
template<int BN, int EPI>
__global__ void __launch_bounds__(2*BN) k_mma(int p0, int p1, int p2, int p3,
                        const float* __restrict__ W1, const float* __restrict__ W2,
                        int woff, const float* __restrict__ bias, int t){
  constexpr int NT = 2*BN;
  constexpr int LDW1 = (BN==64) ? 64 : 128;
  __shared__ unsigned sA[2][16][132];
  __shared__ unsigned sB[2][16][BN+4];
  int tid = threadIdx.x;
  int warp = tid>>5, lane = tid&31;
  int wm = (warp & 1)*64;
  int wn = (warp >> 1)*32;
  int m0 = blockIdx.x*128;

  float c[4][4][4];
  #pragma unroll
  for (int i=0;i<4;i++)
    #pragma unroll
    for (int j=0;j<4;j++)
      #pragma unroll
      for (int e=0;e<4;e++) c[i][j][e] = 0.f;

  const float* panels[4] = { panel(p0)+(size_t)m0*64, panel(p1)+(size_t)m0*64,
                             panel(p2)+(size_t)m0*64, panel(p3)+(size_t)m0*64 };

  auto load_chunk = [&](int cn, int bf){
    int kt = cn>>2, kc = (cn&3)*16;
    const float* Ap = panels[kt];
    for (int i=tid; i<512; i+=NT){
      int m = i>>2, q = i&3;
      float4 v = *(const float4*)(Ap + (size_t)m*64 + kc + q*4);
      sA[bf][q*4+0][m]=to_tf32(v.x);
      sA[bf][q*4+1][m]=to_tf32(v.y);
      sA[bf][q*4+2][m]=to_tf32(v.z);
      sA[bf][q*4+3][m]=to_tf32(v.w);
    }
    for (int i=tid; i<16*BN; i+=NT){
      int kr = i/BN, j = i%BN;
      int wrow = kt*128 + woff + kc + kr;
      float wv = (j < LDW1) ? W1[(size_t)wrow*LDW1 + j]
                            : W2[(size_t)wrow*64 + (j-LDW1)];
      sB[bf][kr][j]=to_tf32(wv);
    }
  };

  load_chunk(0, 0);
  __syncthreads();
  for (int cn=0; cn<16; cn++){
    int bf = cn & 1;
    if (cn+1 < 16) load_chunk(cn+1, bf^1);
    #pragma unroll
    for (int k8=0; k8<16; k8+=8){
      int bk = k8 + (lane&3);
      int bn = wn + (lane>>2);
      unsigned bh[4][2];
      #pragma unroll
      for (int j=0;j<4;j++){
        bh[j][0]=sB[bf][bk][bn+j*8]; bh[j][1]=sB[bf][bk+4][bn+j*8];
      }
      int ac = k8 + (lane&3);
      #pragma unroll
      for (int i=0;i<4;i++){
        int ar = wm + i*16 + (lane>>2);
        unsigned ah[4];
        ah[0]=sA[bf][ac][ar];   ah[1]=sA[bf][ac][ar+8];
        ah[2]=sA[bf][ac+4][ar]; ah[3]=sA[bf][ac+4][ar+8];
        #pragma unroll
        for (int j=0;j<4;j++) mma8(c[i][j], ah, bh[j]);
      }
    }
    __syncthreads();
  }

  #pragma unroll
  for (int i=0;i<4;i++){
    #pragma unroll
    for (int j=0;j<4;j++){
      #pragma unroll
      for (int e=0;e<4;e++){
        int r = (lane>>2) + ((e>=2) ? 8 : 0);
        int col = wn + j*8 + (lane&3)*2 + (e&1);
        size_t row = m0 + wm + i*16 + r;
        float v = c[i][j][e];
        if (EPI==2){
          if (col < 128) g_Gx[row*128 + col] = v;
          else           g_Cx[row*64 + (col-128)] = v;
        }
      }
    }
  }
}

// ============================================================================
// Persistent 12-step loop kernel: grid NBLK x 512. Block bx -> group g=bx>>3,
// sub=bx&7. All inter-block deps are intra-group; per-group 8-block barriers.
// Mutable panel traffic via __ldcg/__stcg (L2 = coherence point).
// ============================================================================
__device__ __forceinline__ void cheb_phase(char* smemraw, int sid,
                                           int d1, int d2, int d3){
  float4* s = (float4*)smemraw;
  const float* src = panel(sid);
  float* o1 = panel(d1);
  float* o2 = panel(d2);
  float* o3 = panel(d3);
  int g  = blockIdx.x >> 3;
  int c0 = (blockIdx.x & 7) * 8;
  int tid = threadIdx.x;
  float4 r0[2][2], r1[2][2], r2[2][2];
  int nz[2], wm[2];
  size_t off[2];
  #pragma unroll
  for (int rr=0; rr<2; rr++){
    int m = tid + rr*512;
    off[rr] = (size_t)(g*1024 + m)*64 + c0;
    r0[rr][0] = __ldcg((const float4*)(src + off[rr]));
    r0[rr][1] = __ldcg((const float4*)(src + off[rr] + 4));
    s[2*m] = r0[rr][0]; s[2*m+1] = r0[rr][1];
    nz[rr] = g_nnz[m];
    int w = nz[rr];
    #pragma unroll
    for (int o=16;o;o>>=1) w = max(w, __shfl_xor_sync(0xffffffffu, w, o));
    wm[rr] = w;
  }
  __syncthreads();
  #pragma unroll
  for (int rr=0; rr<2; rr++)
    gather8(s, tid+rr*512, nz[rr], wm[rr], r1[rr][0], r1[rr][1]);
  __syncthreads();
  #pragma unroll
  for (int rr=0; rr<2; rr++){
    int m = tid + rr*512;
    s[2*m] = r1[rr][0]; s[2*m+1] = r1[rr][1];
    __stcg((float4*)(o1 + off[rr]),     r1[rr][0]);
    __stcg((float4*)(o1 + off[rr] + 4), r1[rr][1]);
  }
  __syncthreads();
  #pragma unroll
  for (int rr=0; rr<2; rr++){
    float4 ta, tb;
    gather8(s, tid+rr*512, nz[rr], wm[rr], ta, tb);
    r2[rr][0] = make_float4(2.f*ta.x - r0[rr][0].x, 2.f*ta.y - r0[rr][0].y,
                            2.f*ta.z - r0[rr][0].z, 2.f*ta.w - r0[rr][0].w);
    r2[rr][1] = make_float4(2.f*tb.x - r0[rr][1].x, 2.f*tb.y - r0[rr][1].y,
                            2.f*tb.z - r0[rr][1].z, 2.f*tb.w - r0[rr][1].w);
  }
  __syncthreads();
  #pragma unroll
  for (int rr=0; rr<2; rr++){
    int m = tid + rr*512;
    s[2*m] = r2[rr][0]; s[2*m+1] = r2[rr][1];
    __stcg((float4*)(o2 + off[rr]),     r2[rr][0]);
    __stcg((float4*)(o2 + off[rr] + 4), r2[rr][1]);
  }
  __syncthreads();
  #pragma unroll
  for (int rr=0; rr<2; rr++){
    float4 ta, tb;
    gather8(s, tid+rr*512, nz[rr], wm[rr], ta, tb);
    float4 r3a = make_float4(2.f*ta.x - r1[rr][0].x, 2.f*ta.y - r1[rr][0].y,
                             2.f*ta.z - r1[rr][0].z, 2.f*ta.w - r1[rr][0].w);
    float4 r3b = make_float4(2.f*tb.x - r1[rr][1].x, 2.f*tb.y - r1[rr][1].y,
                             2.f*tb.z - r1[rr][1].z, 2.f*tb.w - r1[rr][1].w);
    __stcg((float4*)(o3 + off[rr]),     r3a);
    __stcg((float4*)(o3 + off[rr] + 4), r3b);
  }
}

// MMA phase: block = 128-row M-tile, 16 warps, warp-tile 32x16.
template<int BN, int EPI>
__device__ __forceinline__ void mma_phase(char* smemraw,
    int p0, int p1, int p2, int p3,
    const float* __restrict__ W1, int woff,
    const float* __restrict__ bias, int t){
  constexpr int LDW1 = (BN==64) ? 64 : 128;
  constexpr int JN = BN/16;                  // 8 or 4
  constexpr int NJ = (4*JN + 15)/16;         // 2 or 1 jobs per warp
  unsigned (*sA)[132] = (unsigned(*)[132])smemraw;           // [2*16][132]
  unsigned (*sB)[132] = (unsigned(*)[132])(smemraw + 16896); // [2*16][132]
  int tid = threadIdx.x, warp = tid>>5, lane = tid&31;
  int m0 = blockIdx.x*128;

  float c[NJ][2][2][4];
  #pragma unroll
  for (int jw=0;jw<NJ;jw++)
    #pragma unroll
    for (int mi=0;mi<2;mi++)
      #pragma unroll
      for (int ni=0;ni<2;ni++)
        #pragma unroll
        for (int e=0;e<4;e++) c[jw][mi][ni][e] = 0.f;

  const float* panels[4] = { panel(p0)+(size_t)m0*64, panel(p1)+(size_t)m0*64,
                             panel(p2)+(size_t)m0*64, panel(p3)+(size_t)m0*64 };

  auto load_chunk = [&](int cn, int bf){
    int kt = cn>>2, kc = (cn&3)*16;
    const float* Ap = panels[kt];
    {
      int m = tid>>2, q = tid&3;
      float4 v = __ldcg((const float4*)(Ap + (size_t)m*64 + kc + q*4));
      sA[bf*16+q*4+0][m]=to_tf32(v.x);
      sA[bf*16+q*4+1][m]=to_tf32(v.y);
      sA[bf*16+q*4+2][m]=to_tf32(v.z);
      sA[bf*16+q*4+3][m]=to_tf32(v.w);
    }
    if (tid < 4*BN){
      int kr = tid/(BN/4), n4 = tid%(BN/4);
      int wrow = kt*128 + woff + kc + kr;
      float4 wv = *(const float4*)(W1 + (size_t)wrow*LDW1 + n4*4);
      sB[bf*16+kr][n4*4+0]=to_tf32(wv.x);
      sB[bf*16+kr][n4*4+1]=to_tf32(wv.y);
      sB[bf*16+kr][n4*4+2]=to_tf32(wv.z);
      sB[bf*16+kr][n4*4+3]=to_tf32(wv.w);
    }
  };

  load_chunk(0, 0);
  __syncthreads();
  for (int cn=0; cn<16; cn++){
    int bf = cn & 1;
    if (cn+1 < 16) load_chunk(cn+1, bf^1);
    #pragma unroll
    for (int k8=0; k8<16; k8+=8){
      int ac = k8 + (lane&3);
      #pragma unroll
      for (int jw=0; jw<NJ; jw++){
        int job = warp + jw*16;
        int jm = job / JN, jn = job % JN;
        unsigned bh[2][2];
        #pragma unroll
        for (int ni=0; ni<2; ni++){
          int bc = jn*16 + ni*8 + (lane>>2);
          bh[ni][0]=sB[bf*16+ac][bc];
          bh[ni][1]=sB[bf*16+ac+4][bc];
        }
        #pragma unroll
        for (int mi=0; mi<2; mi++){
          int ar = jm*32 + mi*16 + (lane>>2);
          unsigned ah[4];
          ah[0]=sA[bf*16+ac][ar];   ah[1]=sA[bf*16+ac][ar+8];
          ah[2]=sA[bf*16+ac+4][ar]; ah[3]=sA[bf*16+ac+4][ar+8];
          #pragma unroll
          for (int ni=0; ni<2; ni++) mma8(c[jw][mi][ni], ah, bh[ni]);
        }
      }
    }
    __syncthreads();
  }

  #pragma unroll
  for (int jw=0; jw<NJ; jw++){
    int job = warp + jw*16;
    int jm = job / JN, jn = job % JN;
    #pragma unroll
    for (int mi=0; mi<2; mi++){
      #pragma unroll
      for (int ni=0; ni<2; ni++){
        #pragma unroll
        for (int e=0; e<4; e++){
          int r = (lane>>2) + ((e>=2) ? 8 : 0);
          int col = jn*16 + ni*8 + (lane&3)*2 + (e&1);
          size_t row = m0 + jm*32 + mi*16 + r;
          float v = c[jw][mi][ni][e];
          size_t xrow = ((row>>10)*12 + t)*1024 + (row&1023);
          if (EPI==0){
            v += g_Gx[xrow*128 + col] + bias[col];
            float s = 1.f/(1.f+expf(-v));
            if (col < 64)
              __stcg(&g_prh[row*64 + col], s * __ldcg(&g_h[row*64 + col]));
            else
              __stcg(&g_u[row*64 + (col-64)], s);
          } else {
            v += g_Cx[xrow*64 + col] + bias[col];
            float cc = tanhf(v);
            float u = __ldcg(&g_u[row*64 + col]);
            float h = __ldcg(&g_h[row*64 + col]);
            __stcg(&g_h[row*64 + col], u*h + (1.f-u)*cc);
          }
        }
      }
    }
  }
}

__global__ void __launch_bounds__(512) k_loop(
    const float* __restrict__ Wg, const float* __restrict__ bg,
    const float* __restrict__ Wc, const float* __restrict__ bc){
  __shared__ __align__(16) char sm[33792];
  int g = blockIdx.x >> 3;
  for (int t=0; t<12; t++){
    cheb_phase(sm, 4, 5,6,7);
    gbar_g(g);
    mma_phase<128,0>(sm, 4,5,6,7, Wg, 64, bg, t);
    gbar_g(g);
    cheb_phase(sm, 8, 5,6,7);
    gbar_g(g);
    mma_phase<64,1>(sm, 8,5,6,7, Wc, 64, bc, t);
    gbar_g(g);
  }
}

// ---------------- output head ----------------------------------------------
__global__ void __launch_bounds__(256) k_out(const float* __restrict__ Wo1,
                        const float* __restrict__ bo1,
                        const float* __restrict__ Wo2, const float* __restrict__ bo2,
                        float* __restrict__ out){
  __shared__ float sW1[64*64];
  __shared__ float sW2[64*12];
  __shared__ float sb1[64], sb2[12];
  __shared__ float shrow[8][64];
  __shared__ float shid[8][64];
  int tid = threadIdx.x;
  for (int i=tid;i<64*64;i+=256) sW1[i]=Wo1[i];
  for (int i=tid;i<64*12;i+=256) sW2[i]=Wo2[i];
  if (tid<64) sb1[tid]=bo1[tid];
  if (tid<12) sb2[tid]=bo2[tid];
  __syncthreads();
  int warp = tid>>5, lane = tid&31;
  int row = blockIdx.x*8 + warp;            // < 16384 exactly
  shrow[warp][lane]    = g_h[(size_t)row*64 + lane];
  shrow[warp][lane+32] = g_h[(size_t)row*64 + lane + 32];
  __syncwarp();
  #pragma unroll
  for (int half=0; half<2; half++){
    int jj = lane + half*32;
    float a = sb1[jj];
    #pragma unroll
    for (int k=0;k<64;k++) a = fmaf(shrow[warp][k], sW1[k*64+jj], a);
    shid[warp][jj] = fmaxf(a, 0.f);
  }
  __syncwarp();
  if (lane < 12){
    float a = sb2[lane];
    #pragma unroll
    for (int k=0;k<64;k++) a = fmaf(shid[warp][k], sW2[k*12+lane], a);
    int b = row>>10, n = row&1023;
    out[(size_t)(b*12 + lane)*1024 + n] = a;
  }
}

// ---------------- host launcher --------------------------------------------
extern "C" void kernel_launch(void* const* d_in, const int* in_sizes, int n_in,
                              void* d_out, int out_size){
  const float* X     = (const float*)d_in[0];
  const float* ZC    = (const float*)d_in[1];
  const int*   TE    = (const int*)  d_in[2];
  const float* Ls    = (const float*)d_in[3];
  const float* SE    = (const float*)d_in[4];
  const float* Wse1  = (const float*)d_in[5];
  const float* bse1  = (const float*)d_in[6];
  const float* Wse2  = (const float*)d_in[7];
  const float* bse2  = (const float*)d_in[8];
  const float* Wte1  = (const float*)d_in[9];
  const float* bte1  = (const float*)d_in[10];
  const float* Wte2  = (const float*)d_in[11];
  const float* bte2  = (const float*)d_in[12];
  const float* Win1  = (const float*)d_in[13];
  const float* bin1  = (const float*)d_in[14];
  const float* Win2  = (const float*)d_in[15];
  const float* bin2  = (const float*)d_in[16];
  const float* Wconv = (const float*)d_in[17];
  const float* bconv = (const float*)d_in[18];
  const float* Wg    = (const float*)d_in[19];
  const float* bg    = (const float*)d_in[20];
  const float* Wc    = (const float*)d_in[21];
  const float* bc    = (const float*)d_in[22];
  const float* Wo1   = (const float*)d_in[23];
  const float* bo1   = (const float*)d_in[24];
  const float* Wo2   = (const float*)d_in[25];
  const float* bo2   = (const float*)d_in[26];
  float* out = (float*)d_out;

  k_zeroh<<<512,256>>>();
  k_small<<<6,256>>>(SE,Wse1,bse1,Wse2,bse2,Wte1,bte1,Wte2,bte2,TE);
  k_csr<<<32,1024>>>(Ls);
  k_embed<<<6144,256>>>(X,ZC,Wconv,bconv,Win1,bin1,Win2,bin2);

  // precompute: x Chebyshev terms + combined x-part GEMM (Gx | Cx)
  k_cheb3<<<192*8,1024>>>(0, 1,2,3);
  k_mma<192,2><<<1536,384>>>(0,1,2,3, Wg, Wc, 0, Wg, 0);

  // persistent 12-step DCGRU loop (per-group barriers)
  k_loop<<<NBLK,512>>>(Wg, bg, Wc, bc);

  k_out<<<2048,256>>>(Wo1,bo1,Wo2,bo2,out);
}

// round 16
// speedup vs baseline: 1.0859x; 1.0088x over previous
#include <cuda_runtime.h>
#include <math.h>

// Problem constants
#define BB 16
#define PP 12
#define QQ 12
#define NN 1024
#define DD 64
#define HH 32
#define NZCAP 64
#define MPRE (BB*PP*NN)      // 196608 rows for precompute
#define MSTEP (BB*NN)        // 16384 rows per step
#define NBLK 128             // persistent loop grid size

// ---------------- scratch (device globals; no runtime allocation) ----------
__device__ float g_se[NN*HH];
__device__ float g_te[BB*24*HH];
__device__ float g_x [MPRE*64];      // input embedding (b,t,n,64)   id 0
__device__ float g_px1[MPRE*64];     // x Chebyshev terms            id 1
__device__ float g_px2[MPRE*64];     //                              id 2
__device__ float g_px3[MPRE*64];     //                              id 3
__device__ float g_Gx[(size_t)MPRE*128]; // precomputed x-part of gates
__device__ float g_Cx[MPRE*64];          // precomputed x-part of candidate
__device__ float g_h  [MSTEP*64];    // hidden state                 id 4
__device__ float g_ph1[MSTEP*64];    // per-step diffusion panels    id 5
__device__ float g_ph2[MSTEP*64];    //                              id 6
__device__ float g_ph3[MSTEP*64];    //                              id 7
__device__ float g_prh[MSTEP*64];    // r*h                          id 8
__device__ float g_u  [MSTEP*64];    // update gate
__device__ int2  g_ell[NZCAP*NN];    // j-major ELL: [j*NN+m] = {col, val}
__device__ int   g_nnz[NN];
// per-group barriers, padded to 128B lines
__device__ unsigned g_barc[16*32];
__device__ volatile unsigned g_barg[16*32];

__device__ __forceinline__ float* panel(int id){
  switch(id){
    case 0: return g_x;   case 1: return g_px1;
    case 2: return g_px2; case 3: return g_px3;
    case 4: return g_h;   case 5: return g_ph1;
    case 6: return g_ph2; case 7: return g_ph3;
    default: return g_prh;
  }
}

// ---------------- tf32 helpers ---------------------------------------------
__device__ __forceinline__ unsigned to_tf32(float v){
  unsigned h;
  asm("cvt.rna.tf32.f32 %0, %1;" : "=r"(h) : "f"(v));
  return h;
}

__device__ __forceinline__ void mma8(float c[4], const unsigned a[4],
                                     const unsigned b[2]){
  asm volatile(
    "mma.sync.aligned.m16n8k8.row.col.f32.tf32.tf32.f32 "
    "{%0,%1,%2,%3}, {%4,%5,%6,%7}, {%8,%9}, {%0,%1,%2,%3};"
    : "+f"(c[0]), "+f"(c[1]), "+f"(c[2]), "+f"(c[3])
    : "r"(a[0]), "r"(a[1]), "r"(a[2]), "r"(a[3]), "r"(b[0]), "r"(b[1]));
}

// ---------------- per-group grid barrier (8 blocks per group) --------------
__device__ __forceinline__ void gbar_g(int g){
  __threadfence();
  __syncthreads();
  if (threadIdx.x == 0){
    unsigned gen = g_barg[g*32];
    if (atomicAdd(&g_barc[g*32], 1u) == 7u){
      g_barc[g*32] = 0;
      __threadfence();
      g_barg[g*32] = gen + 1u;
    } else {
      while (g_barg[g*32] == gen) __nanosleep(32);
    }
  }
  __syncthreads();
}

// ---------------- small embeddings: se (N,32) and te (B,24,32) -------------
__global__ void k_small(const float* __restrict__ SE,
                        const float* __restrict__ Wse1, const float* __restrict__ bse1,
                        const float* __restrict__ Wse2, const float* __restrict__ bse2,
                        const float* __restrict__ Wte1, const float* __restrict__ bte1,
                        const float* __restrict__ Wte2, const float* __restrict__ bte2,
                        const int* __restrict__ TE){
  int tid = threadIdx.x;
  if (blockIdx.x < 4){
    int n = blockIdx.x*256 + tid;
    float in[32], hid[32];
    #pragma unroll
    for (int k=0;k<32;k++) in[k] = SE[n*32+k];
    #pragma unroll
    for (int j=0;j<32;j++){
      float a = bse1[j];
      #pragma unroll
      for (int k=0;k<32;k++) a = fmaf(in[k], Wse1[k*32+j], a);
      hid[j] = fmaxf(a, 0.f);
    }
    #pragma unroll
    for (int j=0;j<32;j++){
      float a = bse2[j];
      #pragma unroll
      for (int k=0;k<32;k++) a = fmaf(hid[k], Wse2[k*32+j], a);
      g_se[n*32+j] = a;
    }
  } else {
    int i = (blockIdx.x-4)*256 + tid;      // (b,t) flat, t in [0,24)
    if (i < BB*24){
      int day = TE[i*2+0], tod = TE[i*2+1];
      float hid[32];
      #pragma unroll
      for (int j=0;j<32;j++)
        hid[j] = fmaxf(Wte1[day*32+j] + Wte1[(7+tod)*32+j] + bte1[j], 0.f);
      #pragma unroll
      for (int j=0;j<32;j++){
        float a = bte2[j];
        #pragma unroll
        for (int k=0;k<32;k++) a = fmaf(hid[k], Wte2[k*32+j], a);
        g_te[i*32+j] = a;
      }
    }
  }
}

// ---------------- ELL extraction of L_s (j-major, coalesced consumers) -----
__global__ void k_csr(const float* __restrict__ Ls){
  int w = (blockIdx.x*blockDim.x + threadIdx.x) >> 5;
  int lane = threadIdx.x & 31;
  if (w >= NN) return;
  const float* row = Ls + (size_t)w*NN;
  int cnt = 0;
  for (int c0=0;c0<NN;c0+=32){
    float v = row[c0+lane];
    unsigned msk = __ballot_sync(0xffffffffu, v != 0.f);
    if (v != 0.f){
      int pos = cnt + __popc(msk & ((1u<<lane)-1u));
      if (pos < NZCAP) g_ell[pos*NN + w] = make_int2(c0+lane, __float_as_int(v));
    }
    cnt += __popc(msk);
  }
  int nz = cnt < NZCAP ? cnt : NZCAP;
  for (int j = nz + lane; j < NZCAP; j += 32)
    g_ell[j*NN + w] = make_int2(0, 0);
  if (lane==0) g_nnz[w] = nz;
}

// ---------------- input embedding + ZC conv + STE add, writes g_x ----------
__global__ void __launch_bounds__(256) k_embed(const float* __restrict__ X,
                        const float* __restrict__ ZC,
                        const float* __restrict__ Wconv, const float* __restrict__ bconv,
                        const float* __restrict__ W1, const float* __restrict__ b1,
                        const float* __restrict__ W2, const float* __restrict__ b2){
  __shared__ float sWc[98*32];
  __shared__ float sW2[64*32];
  __shared__ float sW1[64], sb1[64], sb2[32], sbc[32];
  __shared__ float srow[8][4][100];
  __shared__ float shid[8][4][64];
  int tid = threadIdx.x;
  for (int i=tid;i<98*32;i+=256) sWc[i]=Wconv[i];
  for (int i=tid;i<64*32;i+=256) sW2[i]=W2[i];
  if (tid<64){ sW1[tid]=W1[tid]; sb1[tid]=b1[tid]; }
  if (tid<32){ sb2[tid]=b2[tid]; sbc[tid]=bconv[tid]; }
  __syncthreads();
  int warp = tid>>5, lane = tid&31;
  int r0 = (blockIdx.x*8 + warp)*4;
  #pragma unroll
  for (int rr=0; rr<4; rr++){
    int row = r0 + rr;
    const float2* z = (const float2*)(ZC + (size_t)row*98);
    for (int i=lane;i<49;i+=32) *(float2*)&srow[warp][rr][2*i] = z[i];
    float xv = X[row];
    shid[warp][rr][lane]    = fmaxf(fmaf(xv, sW1[lane],    sb1[lane]),    0.f);
    shid[warp][rr][lane+32] = fmaxf(fmaf(xv, sW1[lane+32], sb1[lane+32]), 0.f);
  }
  __syncwarp();
  float zacc[4], e[4];
  #pragma unroll
  for (int rr=0;rr<4;rr++){ zacc[rr]=sbc[lane]; e[rr]=sb2[lane]; }
  #pragma unroll 2
  for (int i=0;i<98;i++){
    float w = sWc[i*32+lane];
    #pragma unroll
    for (int rr=0;rr<4;rr++) zacc[rr] = fmaf(srow[warp][rr][i], w, zacc[rr]);
  }
  #pragma unroll 2
  for (int k=0;k<64;k++){
    float w2 = sW2[k*32+lane];
    #pragma unroll
    for (int rr=0;rr<4;rr++) e[rr] = fmaf(shid[warp][rr][k], w2, e[rr]);
  }
  #pragma unroll
  for (int rr=0;rr<4;rr++){
    int row = r0 + rr;
    int b = row/(PP*NN); int pn = row%(PP*NN); int p = pn>>10; int n = pn&1023;
    float ste = g_se[n*32+lane] + g_te[(b*24+p)*32+lane];
    g_x[(size_t)row*64 + lane]      = e[rr] + ste;
    g_x[(size_t)row*64 + 32 + lane] = fmaxf(zacc[rr], 0.f);
  }
}

// ---------------- zero hidden state + barrier init -------------------------
__global__ void k_zeroh(){
  int i0 = blockIdx.x*blockDim.x + threadIdx.x;
  if (i0 < 16*32){ g_barc[i0] = 0; g_barg[i0] = 0; }
  for (int i = i0; i < MSTEP*64; i += gridDim.x*blockDim.x)
    g_h[i] = 0.f;
}

// ---------------- ELL gather: 8 cols for one row from smem tile ------------
__device__ __forceinline__ void gather8(const float4* __restrict__ s,
                                        int m, int nnz, int wm,
                                        float4 &o0, float4 &o1){
  float4 a0 = make_float4(0.f,0.f,0.f,0.f), a1 = a0;
  float4 b0 = a0, b1 = a0;
  for (int j=0; j<wm; j+=2){
    if (j < nnz){
      int2 e = g_ell[j*NN + m];
      float v = __int_as_float(e.y);
      float4 f0 = s[e.x*2], f1 = s[e.x*2+1];
      a0.x=fmaf(v,f0.x,a0.x); a0.y=fmaf(v,f0.y,a0.y);
      a0.z=fmaf(v,f0.z,a0.z); a0.w=fmaf(v,f0.w,a0.w);
      a1.x=fmaf(v,f1.x,a1.x); a1.y=fmaf(v,f1.y,a1.y);
      a1.z=fmaf(v,f1.z,a1.z); a1.w=fmaf(v,f1.w,a1.w);
    }
    if (j+1 < nnz){
      int2 e = g_ell[(j+1)*NN + m];
      float v = __int_as_float(e.y);
      float4 f0 = s[e.x*2], f1 = s[e.x*2+1];
      b0.x=fmaf(v,f0.x,b0.x); b0.y=fmaf(v,f0.y,b0.y);
      b0.z=fmaf(v,f0.z,b0.z); b0.w=fmaf(v,f0.w,b0.w);
      b1.x=fmaf(v,f1.x,b1.x); b1.y=fmaf(v,f1.y,b1.y);
      b1.z=fmaf(v,f1.z,b1.z); b1.w=fmaf(v,f1.w,b1.w);
    }
  }
  o0 = make_float4(a0.x+b0.x, a0.y+b0.y, a0.z+b0.z, a0.w+b0.w);
  o1 = make_float4(a1.x+b1.x, a1.y+b1.y, a1.z+b1.z, a1.w+b1.w);
}

// ---------------- standalone fused Chebyshev (precompute path) -------------
__global__ void __launch_bounds__(1024) k_cheb3(int sid, int d1, int d2, int d3){
  __shared__ float4 s[2048];            // 1024 rows x 8 cols = 32KB
  const float* src = panel(sid);
  float* o1 = panel(d1);
  float* o2 = panel(d2);
  float* o3 = panel(d3);
  int g  = blockIdx.x >> 3;
  int c0 = (blockIdx.x & 7) * 8;
  int m  = threadIdx.x;
  size_t off = (size_t)(g*1024 + m)*64 + c0;
  int nnz = g_nnz[m];
  int wm = nnz;
  #pragma unroll
  for (int o=16;o;o>>=1) wm = max(wm, __shfl_xor_sync(0xffffffffu, wm, o));

  float4 r0a = *(const float4*)(src + off);
  float4 r0b = *(const float4*)(src + off + 4);
  s[2*m] = r0a; s[2*m+1] = r0b;
  __syncthreads();
  float4 r1a, r1b;
  gather8(s, m, nnz, wm, r1a, r1b);
  __syncthreads();
  s[2*m] = r1a; s[2*m+1] = r1b;
  *(float4*)(o1 + off)     = r1a;
  *(float4*)(o1 + off + 4) = r1b;
  __syncthreads();
  float4 ta, tb;
  gather8(s, m, nnz, wm, ta, tb);
  float4 r2a = make_float4(2.f*ta.x - r0a.x, 2.f*ta.y - r0a.y,
                           2.f*ta.z - r0a.z, 2.f*ta.w - r0a.w);
  float4 r2b = make_float4(2.f*tb.x - r0b.x, 2.f*tb.y - r0b.y,
                           2.f*tb.z - r0b.z, 2.f*tb.w - r0b.w);
  __syncthreads();
  s[2*m] = r2a; s[2*m+1] = r2b;
  *(float4*)(o2 + off)     = r2a;
  *(float4*)(o2 + off + 4) = r2b;
  __syncthreads();
  gather8(s, m, nnz, wm, ta, tb);
  float4 r3a = make_float4(2.f*ta.x - r1a.x, 2.f*ta.y - r1a.y,
                           2.f*ta.z - r1a.z, 2.f*ta.w - r1a.w);
  float4 r3b = make_float4(2.f*tb.x - r1b.x, 2.f*tb.y - r1b.y,
                           2.f*tb.z - r1b.z, 2.f*tb.w - r1b.w);
  *(float4*)(o3 + off)     = r3a;
  *(float4*)(o3 + off + 4) = r3b;
}

// ---------------- standalone tf32 MMA GEMM (precompute path, EPI 2) --------
template<int BN, int EPI>
__global__ void __launch_bounds__(2*BN) k_mma(int p0, int p1, int p2, int p3,
                        const float* __restrict__ W1, const float* __restrict__ W2,
                        int woff, const float* __restrict__ bias, int t){
  constexpr int NT = 2*BN;
  constexpr int LDW1 = (BN==64) ? 64 : 128;
  __shared__ unsigned sA[2][16][132];
  __shared__ unsigned sB[2][16][BN+4];
  int tid = threadIdx.x;
  int warp = tid>>5, lane = tid&31;
  int wm = (warp & 1)*64;
  int wn = (warp >> 1)*32;
  int m0 = blockIdx.x*128;

  float c[4][4][4];
  #pragma unroll
  for (int i=0;i<4;i++)
    #pragma unroll
    for (int j=0;j<4;j++)
      #pragma unroll
      for (int e=0;e<4;e++) c[i][j][e] = 0.f;

  const float* panels[4] = { panel(p0)+(size_t)m0*64, panel(p1)+(size_t)m0*64,
                             panel(p2)+(size_t)m0*64, panel(p3)+(size_t)m0*64 };

  auto load_chunk = [&](int cn, int bf){
    int kt = cn>>2, kc = (cn&3)*16;
    const float* Ap = panels[kt];
    for (int i=tid; i<512; i+=NT){
      int m = i>>2, q = i&3;
      float4 v = *(const float4*)(Ap + (size_t)m*64 + kc + q*4);
      sA[bf][q*4+0][m]=to_tf32(v.x);
      sA[bf][q*4+1][m]=to_tf32(v.y);
      sA[bf][q*4+2][m]=to_tf32(v.z);
      sA[bf][q*4+3][m]=to_tf32(v.w);
    }
    for (int i=tid; i<16*BN; i+=NT){
      int kr = i/BN, j = i%BN;
      int wrow = kt*128 + woff + kc + kr;
      float wv = (j < LDW1) ? W1[(size_t)wrow*LDW1 + j]
                            : W2[(size_t)wrow*64 + (j-LDW1)];
      sB[bf][kr][j]=to_tf32(wv);
    }
  };

  load_chunk(0, 0);
  __syncthreads();
  for (int cn=0; cn<16; cn++){
    int bf = cn & 1;
    if (cn+1 < 16) load_chunk(cn+1, bf^1);
    #pragma unroll
    for (int k8=0; k8<16; k8+=8){
      int bk = k8 + (lane&3);
      int bn = wn + (lane>>2);
      unsigned bh[4][2];
      #pragma unroll
      for (int j=0;j<4;j++){
        bh[j][0]=sB[bf][bk][bn+j*8]; bh[j][1]=sB[bf][bk+4][bn+j*8];
      }
      int ac = k8 + (lane&3);
      #pragma unroll
      for (int i=0;i<4;i++){
        int ar = wm + i*16 + (lane>>2);
        unsigned ah[4];
        ah[0]=sA[bf][ac][ar];   ah[1]=sA[bf][ac][ar+8];
        ah[2]=sA[bf][ac+4][ar]; ah[3]=sA[bf][ac+4][ar+8];
        #pragma unroll
        for (int j=0;j<4;j++) mma8(c[i][j], ah, bh[j]);
      }
    }
    __syncthreads();
  }

  #pragma unroll
  for (int i=0;i<4;i++){
    #pragma unroll
    for (int j=0;j<4;j++){
      #pragma unroll
      for (int e=0;e<4;e++){
        int r = (lane>>2) + ((e>=2) ? 8 : 0);
        int col = wn + j*8 + (lane&3)*2 + (e&1);
        size_t row = m0 + wm + i*16 + r;
        float v = c[i][j][e];
        if (EPI==2){
          if (col < 128) g_Gx[row*128 + col] = v;
          else           g_Cx[row*64 + (col-128)] = v;
        }
      }
    }
  }
}

// ============================================================================
// Persistent 12-step loop kernel: grid NBLK x 1024. Block bx -> group g=bx>>3,
// sub=bx&7. All inter-block deps are intra-group; per-group 8-block barriers.
// Mutable panel traffic via __ldcg/__stcg (L2 = coherence point).
// ============================================================================
__device__ __forceinline__ void cheb_phase(char* smemraw, int sid,
                                           int d1, int d2, int d3){
  float4* s = (float4*)smemraw;
  const float* src = panel(sid);
  float* o1 = panel(d1);
  float* o2 = panel(d2);
  float* o3 = panel(d3);
  int g  = blockIdx.x >> 3;
  int c0 = (blockIdx.x & 7) * 8;
  int m  = threadIdx.x;
  size_t off = (size_t)(g*1024 + m)*64 + c0;
  int nnz = g_nnz[m];
  int wm = nnz;
  #pragma unroll
  for (int o=16;o;o>>=1) wm = max(wm, __shfl_xor_sync(0xffffffffu, wm, o));

  float4 r0a = __ldcg((const float4*)(src + off));
  float4 r0b = __ldcg((const float4*)(src + off + 4));
  s[2*m] = r0a; s[2*m+1] = r0b;
  __syncthreads();
  float4 r1a, r1b;
  gather8(s, m, nnz, wm, r1a, r1b);
  __syncthreads();
  s[2*m] = r1a; s[2*m+1] = r1b;
  __stcg((float4*)(o1 + off),     r1a);
  __stcg((float4*)(o1 + off + 4), r1b);
  __syncthreads();
  float4 ta, tb;
  gather8(s, m, nnz, wm, ta, tb);
  float4 r2a = make_float4(2.f*ta.x - r0a.x, 2.f*ta.y - r0a.y,
                           2.f*ta.z - r0a.z, 2.f*ta.w - r0a.w);
  float4 r2b = make_float4(2.f*tb.x - r0b.x, 2.f*tb.y - r0b.y,
                           2.f*tb.z - r0b.z, 2.f*tb.w - r0b.w);
  __syncthreads();
  s[2*m] = r2a; s[2*m+1] = r2b;
  __stcg((float4*)(o2 + off),     r2a);
  __stcg((float4*)(o2 + off + 4), r2b);
  __syncthreads();
  gather8(s, m, nnz, wm, ta, tb);
  float4 r3a = make_float4(2.f*ta.x - r1a.x, 2.f*ta.y - r1a.y,
                           2.f*ta.z - r1a.z, 2.f*ta.w - r1a.w);
  float4 r3b = make_float4(2.f*tb.x - r1b.x, 2.f*tb.y - r1b.y,
                           2.f*tb.z - r1b.z, 2.f*tb.w - r1b.w);
  __stcg((float4*)(o3 + off),     r3a);
  __stcg((float4*)(o3 + off + 4), r3b);
}

// MMA phase: block = 128-row M-tile, 32 warps, warp-job = 16x16 tile.
// Jobs: 8 x (BN/16); warp handles jobs {warp + jw*32}.
template<int BN, int EPI>
__device__ __forceinline__ void mma_phase(char* smemraw,
    int p0, int p1, int p2, int p3,
    const float* __restrict__ W1, int woff,
    const float* __restrict__ bias, int t){
  constexpr int LDW1 = (BN==64) ? 64 : 128;
  constexpr int JN = BN/16;                  // 8 or 4
  constexpr int NJ = (8*JN + 31)/32;         // 2 or 1 jobs per warp
  unsigned (*sA)[132] = (unsigned(*)[132])smemraw;           // [2*16][132]
  unsigned (*sB)[132] = (unsigned(*)[132])(smemraw + 16896); // [2*16][132]
  int tid = threadIdx.x, warp = tid>>5, lane = tid&31;
  int m0 = blockIdx.x*128;

  float c[NJ][2][4];
  #pragma unroll
  for (int jw=0;jw<NJ;jw++)
    #pragma unroll
    for (int ni=0;ni<2;ni++)
      #pragma unroll
      for (int e=0;e<4;e++) c[jw][ni][e] = 0.f;

  const float* panels[4] = { panel(p0)+(size_t)m0*64, panel(p1)+(size_t)m0*64,
                             panel(p2)+(size_t)m0*64, panel(p3)+(size_t)m0*64 };

  auto load_chunk = [&](int cn, int bf){
    int kt = cn>>2, kc = (cn&3)*16;
    if (tid < 512){
      const float* Ap = panels[kt];
      int m = tid>>2, q = tid&3;
      float4 v = __ldcg((const float4*)(Ap + (size_t)m*64 + kc + q*4));
      sA[bf*16+q*4+0][m]=to_tf32(v.x);
      sA[bf*16+q*4+1][m]=to_tf32(v.y);
      sA[bf*16+q*4+2][m]=to_tf32(v.z);
      sA[bf*16+q*4+3][m]=to_tf32(v.w);
    } else {
      int t2 = tid - 512;
      if (t2 < 4*BN){
        int kr = t2/(BN/4), n4 = t2%(BN/4);
        int wrow = kt*128 + woff + kc + kr;
        float4 wv = *(const float4*)(W1 + (size_t)wrow*LDW1 + n4*4);
        sB[bf*16+kr][n4*4+0]=to_tf32(wv.x);
        sB[bf*16+kr][n4*4+1]=to_tf32(wv.y);
        sB[bf*16+kr][n4*4+2]=to_tf32(wv.z);
        sB[bf*16+kr][n4*4+3]=to_tf32(wv.w);
      }
    }
  };

  load_chunk(0, 0);
  __syncthreads();
  for (int cn=0; cn<16; cn++){
    int bf = cn & 1;
    if (cn+1 < 16) load_chunk(cn+1, bf^1);
    #pragma unroll
    for (int k8=0; k8<16; k8+=8){
      int ac = k8 + (lane&3);
      #pragma unroll
      for (int jw=0; jw<NJ; jw++){
        int job = warp + jw*32;
        int jm = job / JN, jn = job % JN;
        unsigned bh[2][2];
        #pragma unroll
        for (int ni=0; ni<2; ni++){
          int bc = jn*16 + ni*8 + (lane>>2);
          bh[ni][0]=sB[bf*16+ac][bc];
          bh[ni][1]=sB[bf*16+ac+4][bc];
        }
        int ar = jm*16 + (lane>>2);
        unsigned ah[4];
        ah[0]=sA[bf*16+ac][ar];   ah[1]=sA[bf*16+ac][ar+8];
        ah[2]=sA[bf*16+ac+4][ar]; ah[3]=sA[bf*16+ac+4][ar+8];
        #pragma unroll
        for (int ni=0; ni<2; ni++) mma8(c[jw][ni], ah, bh[ni]);
      }
    }
    __syncthreads();
  }

  #pragma unroll
  for (int jw=0; jw<NJ; jw++){
    int job = warp + jw*32;
    int jm = job / JN, jn = job % JN;
    #pragma unroll
    for (int ni=0; ni<2; ni++){
      #pragma unroll
      for (int e=0; e<4; e++){
        int r = (lane>>2) + ((e>=2) ? 8 : 0);
        int col = jn*16 + ni*8 + (lane&3)*2 + (e&1);
        size_t row = m0 + jm*16 + r;
        float v = c[jw][ni][e];
        size_t xrow = ((row>>10)*12 + t)*1024 + (row&1023);
        if (EPI==0){
          v += g_Gx[xrow*128 + col] + bias[col];
          float s = 1.f/(1.f+expf(-v));
          if (col < 64)
            __stcg(&g_prh[row*64 + col], s * __ldcg(&g_h[row*64 + col]));
          else
            __stcg(&g_u[row*64 + (col-64)], s);
        } else {
          v += g_Cx[xrow*64 + col] + bias[col];
          float cc = tanhf(v);
          float u = __ldcg(&g_u[row*64 + col]);
          float h = __ldcg(&g_h[row*64 + col]);
          __stcg(&g_h[row*64 + col], u*h + (1.f-u)*cc);
        }
      }
    }
  }
}

__global__ void __launch_bounds__(1024) k_loop(
    const float* __restrict__ Wg, const float* __restrict__ bg,
    const float* __restrict__ Wc, const float* __restrict__ bc){
  __shared__ __align__(16) char sm[33792];
  int g = blockIdx.x >> 3;
  for (int t=0; t<12; t++){
    cheb_phase(sm, 4, 5,6,7);
    gbar_g(g);
    mma_phase<128,0>(sm, 4,5,6,7, Wg, 64, bg, t);
    gbar_g(g);
    cheb_phase(sm, 8, 5,6,7);
    gbar_g(g);
    mma_phase<64,1>(sm, 8,5,6,7, Wc, 64, bc, t);
    gbar_g(g);
  }
}

// ---------------- output head ----------------------------------------------
__global__ void __launch_bounds__(256) k_out(const float* __restrict__ Wo1,
                        const float* __restrict__ bo1,
                        const float* __restrict__ Wo2, const float* __restrict__ bo2,
                        float* __restrict__ out){
  __shared__ float sW1[64*64];
  __shared__ float sW2[64*12];
  __shared__ float sb1[64], sb2[12];
  __shared__ float shrow[8][64];
  __shared__ float shid[8][64];
  int tid = threadIdx.x;
  for (int i=tid;i<64*64;i+=256) sW1[i]=Wo1[i];
  for (int i=tid;i<64*12;i+=256) sW2[i]=Wo2[i];
  if (tid<64) sb1[tid]=bo1[tid];
  if (tid<12) sb2[tid]=bo2[tid];
  __syncthreads();
  int warp = tid>>5, lane = tid&31;
  int row = blockIdx.x*8 + warp;            // < 16384 exactly
  shrow[warp][lane]    = g_h[(size_t)row*64 + lane];
  shrow[warp][lane+32] = g_h[(size_t)row*64 + lane + 32];
  __syncwarp();
  #pragma unroll
  for (int half=0; half<2; half++){
    int jj = lane + half*32;
    float a = sb1[jj];
    #pragma unroll
    for (int k=0;k<64;k++) a = fmaf(shrow[warp][k], sW1[k*64+jj], a);
    shid[warp][jj] = fmaxf(a, 0.f);
  }
  __syncwarp();
  if (lane < 12){
    float a = sb2[lane];
    #pragma unroll
    for (int k=0;k<64;k++) a = fmaf(shid[warp][k], sW2[k*12+lane], a);
    int b = row>>10, n = row&1023;
    out[(size_t)(b*12 + lane)*1024 + n] = a;
  }
}

// ---------------- host launcher --------------------------------------------
extern "C" void kernel_launch(void* const* d_in, const int* in_sizes, int n_in,
                              void* d_out, int out_size){
  const float* X     = (const float*)d_in[0];
  const float* ZC    = (const float*)d_in[1];
  const int*   TE    = (const int*)  d_in[2];
  const float* Ls    = (const float*)d_in[3];
  const float* SE    = (const float*)d_in[4];
  const float* Wse1  = (const float*)d_in[5];
  const float* bse1  = (const float*)d_in[6];
  const float* Wse2  = (const float*)d_in[7];
  const float* bse2  = (const float*)d_in[8];
  const float* Wte1  = (const float*)d_in[9];
  const float* bte1  = (const float*)d_in[10];
  const float* Wte2  = (const float*)d_in[11];
  const float* bte2  = (const float*)d_in[12];
  const float* Win1  = (const float*)d_in[13];
  const float* bin1  = (const float*)d_in[14];
  const float* Win2  = (const float*)d_in[15];
  const float* bin2  = (const float*)d_in[16];
  const float* Wconv = (const float*)d_in[17];
  const float* bconv = (const float*)d_in[18];
  const float* Wg    = (const float*)d_in[19];
  const float* bg    = (const float*)d_in[20];
  const float* Wc    = (const float*)d_in[21];
  const float* bc    = (const float*)d_in[22];
  const float* Wo1   = (const float*)d_in[23];
  const float* bo1   = (const float*)d_in[24];
  const float* Wo2   = (const float*)d_in[25];
  const float* bo2   = (const float*)d_in[26];
  float* out = (float*)d_out;

  k_zeroh<<<512,256>>>();
  k_small<<<6,256>>>(SE,Wse1,bse1,Wse2,bse2,Wte1,bte1,Wte2,bte2,TE);
  k_csr<<<32,1024>>>(Ls);
  k_embed<<<6144,256>>>(X,ZC,Wconv,bconv,Win1,bin1,Win2,bin2);

  // precompute: x Chebyshev terms + combined x-part GEMM (Gx | Cx)
  k_cheb3<<<192*8,1024>>>(0, 1,2,3);
  k_mma<192,2><<<1536,384>>>(0,1,2,3, Wg, Wc, 0, Wg, 0);

  // persistent 12-step DCGRU loop (per-group barriers, 1024 threads)
  k_loop<<<NBLK,1024>>>(Wg, bg, Wc, bc);

  k_out<<<2048,256>>>(Wo1,bo1,Wo2,bo2,out);
}

// round 17
// speedup vs baseline: 1.1016x; 1.0144x over previous
#include <cuda_runtime.h>
#include <math.h>

// Problem constants
#define BB 16
#define PP 12
#define QQ 12
#define NN 1024
#define DD 64
#define HH 32
#define NZCAP 64
#define MPRE (BB*PP*NN)      // 196608 rows for precompute
#define MSTEP (BB*NN)        // 16384 rows per step
#define NBLK 128             // persistent loop grid size

// ---------------- scratch (device globals; no runtime allocation) ----------
__device__ float g_se[NN*HH];
__device__ float g_te[BB*24*HH];
__device__ float g_x [MPRE*64];      // input embedding (b,t,n,64)   id 0
__device__ float g_px1[MPRE*64];     // x Chebyshev terms            id 1
__device__ float g_px2[MPRE*64];     //                              id 2
__device__ float g_px3[MPRE*64];     //                              id 3
__device__ float g_Gx[(size_t)MPRE*128]; // precomputed x-part of gates
__device__ float g_Cx[MPRE*64];          // precomputed x-part of candidate
__device__ float g_h  [MSTEP*64];    // hidden state                 id 4
__device__ float g_ph1[MSTEP*64];    // per-step diffusion panels    id 5
__device__ float g_ph2[MSTEP*64];    //                              id 6
__device__ float g_ph3[MSTEP*64];    //                              id 7
__device__ float g_prh[MSTEP*64];    // r*h                          id 8
__device__ float g_u  [MSTEP*64];    // update gate
__device__ int2  g_ell[NZCAP*NN];    // j-major ELL: [j*NN+m] = {col, val}
__device__ int   g_nnz[NN];
// per-group barriers, padded to 128B lines
__device__ unsigned g_barc[16*32];
__device__ volatile unsigned g_barg[16*32];

__device__ __forceinline__ float* panel(int id){
  switch(id){
    case 0: return g_x;   case 1: return g_px1;
    case 2: return g_px2; case 3: return g_px3;
    case 4: return g_h;   case 5: return g_ph1;
    case 6: return g_ph2; case 7: return g_ph3;
    default: return g_prh;
  }
}

// ---------------- tf32 helpers ---------------------------------------------
__device__ __forceinline__ unsigned to_tf32(float v){
  unsigned h;
  asm("cvt.rna.tf32.f32 %0, %1;" : "=r"(h) : "f"(v));
  return h;
}

__device__ __forceinline__ void mma8(float c[4], const unsigned a[4],
                                     const unsigned b[2]){
  asm volatile(
    "mma.sync.aligned.m16n8k8.row.col.f32.tf32.tf32.f32 "
    "{%0,%1,%2,%3}, {%4,%5,%6,%7}, {%8,%9}, {%0,%1,%2,%3};"
    : "+f"(c[0]), "+f"(c[1]), "+f"(c[2]), "+f"(c[3])
    : "r"(a[0]), "r"(a[1]), "r"(a[2]), "r"(a[3]), "r"(b[0]), "r"(b[1]));
}

// ---------------- per-group grid barrier (8 blocks per group) --------------
__device__ __forceinline__ void gbar_g(int g){
  __threadfence();
  __syncthreads();
  if (threadIdx.x == 0){
    unsigned gen = g_barg[g*32];
    if (atomicAdd(&g_barc[g*32], 1u) == 7u){
      g_barc[g*32] = 0;
      __threadfence();
      g_barg[g*32] = gen + 1u;
    } else {
      while (g_barg[g*32] == gen) __nanosleep(32);
    }
  }
  __syncthreads();
}

// ---------------- fused prologue: se/te embeddings, ELL, h=0, barriers -----
__global__ void __launch_bounds__(256) k_pre(const float* __restrict__ SE,
                        const float* __restrict__ Wse1, const float* __restrict__ bse1,
                        const float* __restrict__ Wse2, const float* __restrict__ bse2,
                        const float* __restrict__ Wte1, const float* __restrict__ bte1,
                        const float* __restrict__ Wte2, const float* __restrict__ bte2,
                        const int* __restrict__ TE,
                        const float* __restrict__ Ls){
  int bx = blockIdx.x, tid = threadIdx.x;
  if (bx < 4){
    int n = bx*256 + tid;
    float in[32], hid[32];
    #pragma unroll
    for (int k=0;k<32;k++) in[k] = SE[n*32+k];
    #pragma unroll
    for (int j=0;j<32;j++){
      float a = bse1[j];
      #pragma unroll
      for (int k=0;k<32;k++) a = fmaf(in[k], Wse1[k*32+j], a);
      hid[j] = fmaxf(a, 0.f);
    }
    #pragma unroll
    for (int j=0;j<32;j++){
      float a = bse2[j];
      #pragma unroll
      for (int k=0;k<32;k++) a = fmaf(hid[k], Wse2[k*32+j], a);
      g_se[n*32+j] = a;
    }
  } else if (bx < 6){
    int i = (bx-4)*256 + tid;              // (b,t) flat, t in [0,24)
    if (i < BB*24){
      int day = TE[i*2+0], tod = TE[i*2+1];
      float hid[32];
      #pragma unroll
      for (int j=0;j<32;j++)
        hid[j] = fmaxf(Wte1[day*32+j] + Wte1[(7+tod)*32+j] + bte1[j], 0.f);
      #pragma unroll
      for (int j=0;j<32;j++){
        float a = bte2[j];
        #pragma unroll
        for (int k=0;k<32;k++) a = fmaf(hid[k], Wte2[k*32+j], a);
        g_te[i*32+j] = a;
      }
    }
  } else if (bx < 134){
    int w = (bx-6)*8 + (tid>>5);           // 0..1023
    int lane = tid & 31;
    const float* row = Ls + (size_t)w*NN;
    int cnt = 0;
    for (int c0=0;c0<NN;c0+=32){
      float v = row[c0+lane];
      unsigned msk = __ballot_sync(0xffffffffu, v != 0.f);
      if (v != 0.f){
        int pos = cnt + __popc(msk & ((1u<<lane)-1u));
        if (pos < NZCAP) g_ell[pos*NN + w] = make_int2(c0+lane, __float_as_int(v));
      }
      cnt += __popc(msk);
    }
    int nz = cnt < NZCAP ? cnt : NZCAP;
    for (int j = nz + lane; j < NZCAP; j += 32)
      g_ell[j*NN + w] = make_int2(0, 0);
    if (lane==0) g_nnz[w] = nz;
  } else {
    int i0 = (bx-134)*256 + tid;
    if (i0 < 16*32){ g_barc[i0] = 0; g_barg[i0] = 0; }
    for (int i = i0; i < MSTEP*64; i += 378*256)
      g_h[i] = 0.f;
  }
}

// ---------------- input embedding + ZC conv + STE add, writes g_x ----------
__global__ void __launch_bounds__(256) k_embed(const float* __restrict__ X,
                        const float* __restrict__ ZC,
                        const float* __restrict__ Wconv, const float* __restrict__ bconv,
                        const float* __restrict__ W1, const float* __restrict__ b1,
                        const float* __restrict__ W2, const float* __restrict__ b2){
  __shared__ float sWc[98*32];
  __shared__ float sW2[64*32];
  __shared__ float sW1[64], sb1[64], sb2[32], sbc[32];
  __shared__ float srow[8][4][100];
  __shared__ float shid[8][4][64];
  int tid = threadIdx.x;
  for (int i=tid;i<98*32;i+=256) sWc[i]=Wconv[i];
  for (int i=tid;i<64*32;i+=256) sW2[i]=W2[i];
  if (tid<64){ sW1[tid]=W1[tid]; sb1[tid]=b1[tid]; }
  if (tid<32){ sb2[tid]=b2[tid]; sbc[tid]=bconv[tid]; }
  __syncthreads();
  int warp = tid>>5, lane = tid&31;
  int r0 = (blockIdx.x*8 + warp)*4;
  #pragma unroll
  for (int rr=0; rr<4; rr++){
    int row = r0 + rr;
    const float2* z = (const float2*)(ZC + (size_t)row*98);
    for (int i=lane;i<49;i+=32) *(float2*)&srow[warp][rr][2*i] = z[i];
    float xv = X[row];
    shid[warp][rr][lane]    = fmaxf(fmaf(xv, sW1[lane],    sb1[lane]),    0.f);
    shid[warp][rr][lane+32] = fmaxf(fmaf(xv, sW1[lane+32], sb1[lane+32]), 0.f);
  }
  __syncwarp();
  float zacc[4], e[4];
  #pragma unroll
  for (int rr=0;rr<4;rr++){ zacc[rr]=sbc[lane]; e[rr]=sb2[lane]; }
  #pragma unroll 2
  for (int i=0;i<98;i++){
    float w = sWc[i*32+lane];
    #pragma unroll
    for (int rr=0;rr<4;rr++) zacc[rr] = fmaf(srow[warp][rr][i], w, zacc[rr]);
  }
  #pragma unroll 2
  for (int k=0;k<64;k++){
    float w2 = sW2[k*32+lane];
    #pragma unroll
    for (int rr=0;rr<4;rr++) e[rr] = fmaf(shid[warp][rr][k], w2, e[rr]);
  }
  #pragma unroll
  for (int rr=0;rr<4;rr++){
    int row = r0 + rr;
    int b = row/(PP*NN); int pn = row%(PP*NN); int p = pn>>10; int n = pn&1023;
    float ste = g_se[n*32+lane] + g_te[(b*24+p)*32+lane];
    g_x[(size_t)row*64 + lane]      = e[rr] + ste;
    g_x[(size_t)row*64 + 32 + lane] = fmaxf(zacc[rr], 0.f);
  }
}

// ---------------- ELL gather: 8 cols for one row from smem tile ------------
__device__ __forceinline__ void gather8(const float4* __restrict__ s,
                                        int m, int nnz, int wm,
                                        float4 &o0, float4 &o1){
  float4 a0 = make_float4(0.f,0.f,0.f,0.f), a1 = a0;
  float4 b0 = a0, b1 = a0;
  for (int j=0; j<wm; j+=2){
    if (j < nnz){
      int2 e = g_ell[j*NN + m];
      float v = __int_as_float(e.y);
      float4 f0 = s[e.x*2], f1 = s[e.x*2+1];
      a0.x=fmaf(v,f0.x,a0.x); a0.y=fmaf(v,f0.y,a0.y);
      a0.z=fmaf(v,f0.z,a0.z); a0.w=fmaf(v,f0.w,a0.w);
      a1.x=fmaf(v,f1.x,a1.x); a1.y=fmaf(v,f1.y,a1.y);
      a1.z=fmaf(v,f1.z,a1.z); a1.w=fmaf(v,f1.w,a1.w);
    }
    if (j+1 < nnz){
      int2 e = g_ell[(j+1)*NN + m];
      float v = __int_as_float(e.y);
      float4 f0 = s[e.x*2], f1 = s[e.x*2+1];
      b0.x=fmaf(v,f0.x,b0.x); b0.y=fmaf(v,f0.y,b0.y);
      b0.z=fmaf(v,f0.z,b0.z); b0.w=fmaf(v,f0.w,b0.w);
      b1.x=fmaf(v,f1.x,b1.x); b1.y=fmaf(v,f1.y,b1.y);
      b1.z=fmaf(v,f1.z,b1.z); b1.w=fmaf(v,f1.w,b1.w);
    }
  }
  o0 = make_float4(a0.x+b0.x, a0.y+b0.y, a0.z+b0.z, a0.w+b0.w);
  o1 = make_float4(a1.x+b1.x, a1.y+b1.y, a1.z+b1.z, a1.w+b1.w);
}

// ---------------- standalone fused Chebyshev (precompute path) -------------
__global__ void __launch_bounds__(1024) k_cheb3(int sid, int d1, int d2, int d3){
  __shared__ float4 s[2048];            // 1024 rows x 8 cols = 32KB
  const float* src = panel(sid);
  float* o1 = panel(d1);
  float* o2 = panel(d2);
  float* o3 = panel(d3);
  int g  = blockIdx.x >> 3;
  int c0 = (blockIdx.x & 7) * 8;
  int m  = threadIdx.x;
  size_t off = (size_t)(g*1024 + m)*64 + c0;
  int nnz = g_nnz[m];
  int wm = nnz;
  #pragma unroll
  for (int o=16;o;o>>=1) wm = max(wm, __shfl_xor_sync(0xffffffffu, wm, o));

  float4 r0a = *(const float4*)(src + off);
  float4 r0b = *(const float4*)(src + off + 4);
  s[2*m] = r0a; s[2*m+1] = r0b;
  __syncthreads();
  float4 r1a, r1b;
  gather8(s, m, nnz, wm, r1a, r1b);
  __syncthreads();
  s[2*m] = r1a; s[2*m+1] = r1b;
  *(float4*)(o1 + off)     = r1a;
  *(float4*)(o1 + off + 4) = r1b;
  __syncthreads();
  float4 ta, tb;
  gather8(s, m, nnz, wm, ta, tb);
  float4 r2a = make_float4(2.f*ta.x - r0a.x, 2.f*ta.y - r0a.y,
                           2.f*ta.z - r0a.z, 2.f*ta.w - r0a.w);
  float4 r2b = make_float4(2.f*tb.x - r0b.x, 2.f*tb.y - r0b.y,
                           2.f*tb.z - r0b.z, 2.f*tb.w - r0b.w);
  __syncthreads();
  s[2*m] = r2a; s[2*m+1] = r2b;
  *(float4*)(o2 + off)     = r2a;
  *(float4*)(o2 + off + 4) = r2b;
  __syncthreads();
  gather8(s, m, nnz, wm, ta, tb);
  float4 r3a = make_float4(2.f*ta.x - r1a.x, 2.f*ta.y - r1a.y,
                           2.f*ta.z - r1a.z, 2.f*ta.w - r1a.w);
  float4 r3b = make_float4(2.f*tb.x - r1b.x, 2.f*tb.y - r1b.y,
                           2.f*tb.z - r1b.z, 2.f*tb.w - r1b.w);
  *(float4*)(o3 + off)     = r3a;
  *(float4*)(o3 + off + 4) = r3b;
}

// ---------------- standalone tf32 MMA GEMM (precompute path, EPI 2) --------
template<int BN, int EPI>
__global__ void __launch_bounds__(2*BN) k_mma(int p0, int p1, int p2, int p3,
                        const float* __restrict__ W1, const float* __restrict__ W2,
                        int woff, const float* __restrict__ bias, int t){
  constexpr int NT = 2*BN;
  constexpr int LDW1 = (BN==64) ? 64 : 128;
  __shared__ unsigned sA[2][16][132];
  __shared__ unsigned sB[2][16][BN+4];
  int tid = threadIdx.x;
  int warp = tid>>5, lane = tid&31;
  int wm = (warp & 1)*64;
  int wn = (warp >> 1)*32;
  int m0 = blockIdx.x*128;

  float c[4][4][4];
  #pragma unroll
  for (int i=0;i<4;i++)
    #pragma unroll
    for (int j=0;j<4;j++)
      #pragma unroll
      for (int e=0;e<4;e++) c[i][j][e] = 0.f;

  const float* panels[4] = { panel(p0)+(size_t)m0*64, panel(p1)+(size_t)m0*64,
                             panel(p2)+(size_t)m0*64, panel(p3)+(size_t)m0*64 };

  auto load_chunk = [&](int cn, int bf){
    int kt = cn>>2, kc = (cn&3)*16;
    const float* Ap = panels[kt];
    for (int i=tid; i<512; i+=NT){
      int m = i>>2, q = i&3;
      float4 v = *(const float4*)(Ap + (size_t)m*64 + kc + q*4);
      sA[bf][q*4+0][m]=to_tf32(v.x);
      sA[bf][q*4+1][m]=to_tf32(v.y);
      sA[bf][q*4+2][m]=to_tf32(v.z);
      sA[bf][q*4+3][m]=to_tf32(v.w);
    }
    for (int i=tid; i<16*BN; i+=NT){
      int kr = i/BN, j = i%BN;
      int wrow = kt*128 + woff + kc + kr;
      float wv = (j < LDW1) ? W1[(size_t)wrow*LDW1 + j]
                            : W2[(size_t)wrow*64 + (j-LDW1)];
      sB[bf][kr][j]=to_tf32(wv);
    }
  };

  load_chunk(0, 0);
  __syncthreads();
  for (int cn=0; cn<16; cn++){
    int bf = cn & 1;
    if (cn+1 < 16) load_chunk(cn+1, bf^1);
    #pragma unroll
    for (int k8=0; k8<16; k8+=8){
      int bk = k8 + (lane&3);
      int bn = wn + (lane>>2);
      unsigned bh[4][2];
      #pragma unroll
      for (int j=0;j<4;j++){
        bh[j][0]=sB[bf][bk][bn+j*8]; bh[j][1]=sB[bf][bk+4][bn+j*8];
      }
      int ac = k8 + (lane&3);
      #pragma unroll
      for (int i=0;i<4;i++){
        int ar = wm + i*16 + (lane>>2);
        unsigned ah[4];
        ah[0]=sA[bf][ac][ar];   ah[1]=sA[bf][ac][ar+8];
        ah[2]=sA[bf][ac+4][ar]; ah[3]=sA[bf][ac+4][ar+8];
        #pragma unroll
        for (int j=0;j<4;j++) mma8(c[i][j], ah, bh[j]);
      }
    }
    __syncthreads();
  }

  #pragma unroll
  for (int i=0;i<4;i++){
    #pragma unroll
    for (int j=0;j<4;j++){
      #pragma unroll
      for (int e=0;e<4;e++){
        int r = (lane>>2) + ((e>=2) ? 8 : 0);
        int col = wn + j*8 + (lane&3)*2 + (e&1);
        size_t row = m0 + wm + i*16 + r;
        float v = c[i][j][e];
        if (EPI==2){
          if (col < 128) g_Gx[row*128 + col] = v;
          else           g_Cx[row*64 + (col-128)] = v;
        }
      }
    }
  }
}

// ============================================================================
// Persistent 12-step loop kernel: grid NBLK x 1024. Block bx -> group g=bx>>3,
// sub=bx&7. All inter-block deps are intra-group; per-group 8-block barriers.
// Mutable panel traffic via __ldcg/__stcg (L2 = coherence point).
// ============================================================================
__device__ __forceinline__ void cheb_phase(char* smemraw, int sid,
                                           int d1, int d2, int d3){
  float4* s = (float4*)smemraw;
  const float* src = panel(sid);
  float* o1 = panel(d1);
  float* o2 = panel(d2);
  float* o3 = panel(d3);
  int g  = blockIdx.x >> 3;
  int c0 = (blockIdx.x & 7) * 8;
  int m  = threadIdx.x;
  size_t off = (size_t)(g*1024 + m)*64 + c0;
  int nnz = g_nnz[m];
  int wm = nnz;
  #pragma unroll
  for (int o=16;o;o>>=1) wm = max(wm, __shfl_xor_sync(0xffffffffu, wm, o));

  float4 r0a = __ldcg((const float4*)(src + off));
  float4 r0b = __ldcg((const float4*)(src + off + 4));
  s[2*m] = r0a; s[2*m+1] = r0b;
  __syncthreads();
  float4 r1a, r1b;
  gather8(s, m, nnz, wm, r1a, r1b);
  __syncthreads();
  s[2*m] = r1a; s[2*m+1] = r1b;
  __stcg((float4*)(o1 + off),     r1a);
  __stcg((float4*)(o1 + off + 4), r1b);
  __syncthreads();
  float4 ta, tb;
  gather8(s, m, nnz, wm, ta, tb);
  float4 r2a = make_float4(2.f*ta.x - r0a.x, 2.f*ta.y - r0a.y,
                           2.f*ta.z - r0a.z, 2.f*ta.w - r0a.w);
  float4 r2b = make_float4(2.f*tb.x - r0b.x, 2.f*tb.y - r0b.y,
                           2.f*tb.z - r0b.z, 2.f*tb.w - r0b.w);
  __syncthreads();
  s[2*m] = r2a; s[2*m+1] = r2b;
  __stcg((float4*)(o2 + off),     r2a);
  __stcg((float4*)(o2 + off + 4), r2b);
  __syncthreads();
  gather8(s, m, nnz, wm, ta, tb);
  float4 r3a = make_float4(2.f*ta.x - r1a.x, 2.f*ta.y - r1a.y,
                           2.f*ta.z - r1a.z, 2.f*ta.w - r1a.w);
  float4 r3b = make_float4(2.f*tb.x - r1b.x, 2.f*tb.y - r1b.y,
                           2.f*tb.z - r1b.z, 2.f*tb.w - r1b.w);
  __stcg((float4*)(o3 + off),     r3a);
  __stcg((float4*)(o3 + off + 4), r3b);
}

// MMA phase: block = 128-row M-tile, 32 warps, warp-job = 16x16 tile.
// Software-pipelined: fetch(cn+1) -> compute(cn) -> commit(cn+1) -> sync.
template<int BN, int EPI>
__device__ __forceinline__ void mma_phase(char* smemraw,
    int p0, int p1, int p2, int p3,
    const float* __restrict__ W1, int woff,
    const float* __restrict__ bias, int t){
  constexpr int LDW1 = (BN==64) ? 64 : 128;
  constexpr int JN = BN/16;                  // 8 or 4
  constexpr int NJ = (8*JN + 31)/32;         // 2 or 1 jobs per warp
  unsigned (*sA)[132] = (unsigned(*)[132])smemraw;           // [2*16][132]
  unsigned (*sB)[132] = (unsigned(*)[132])(smemraw + 16896); // [2*16][132]
  int tid = threadIdx.x, warp = tid>>5, lane = tid&31;
  int m0 = blockIdx.x*128;

  float c[NJ][2][4];
  #pragma unroll
  for (int jw=0;jw<NJ;jw++)
    #pragma unroll
    for (int ni=0;ni<2;ni++)
      #pragma unroll
      for (int e=0;e<4;e++) c[jw][ni][e] = 0.f;

  const float* panels[4] = { panel(p0)+(size_t)m0*64, panel(p1)+(size_t)m0*64,
                             panel(p2)+(size_t)m0*64, panel(p3)+(size_t)m0*64 };

  auto fetch = [&](int cn)->float4 {
    int kt = cn>>2, kc = (cn&3)*16;
    if (tid < 512){
      int m = tid>>2, q = tid&3;
      return __ldcg((const float4*)(panels[kt] + (size_t)m*64 + kc + q*4));
    } else {
      int t2 = tid - 512;
      if (t2 < 4*BN){
        int kr = t2/(BN/4), n4 = t2%(BN/4);
        int wrow = kt*128 + woff + kc + kr;
        return *(const float4*)(W1 + (size_t)wrow*LDW1 + n4*4);
      }
    }
    return make_float4(0.f,0.f,0.f,0.f);
  };
  auto commit = [&](float4 v, int bf){
    if (tid < 512){
      int m = tid>>2, q = tid&3;
      sA[bf*16+q*4+0][m]=to_tf32(v.x);
      sA[bf*16+q*4+1][m]=to_tf32(v.y);
      sA[bf*16+q*4+2][m]=to_tf32(v.z);
      sA[bf*16+q*4+3][m]=to_tf32(v.w);
    } else {
      int t2 = tid - 512;
      if (t2 < 4*BN){
        int kr = t2/(BN/4), n4 = t2%(BN/4);
        sB[bf*16+kr][n4*4+0]=to_tf32(v.x);
        sB[bf*16+kr][n4*4+1]=to_tf32(v.y);
        sB[bf*16+kr][n4*4+2]=to_tf32(v.z);
        sB[bf*16+kr][n4*4+3]=to_tf32(v.w);
      }
    }
  };

  float4 v0 = fetch(0);
  commit(v0, 0);
  __syncthreads();
  for (int cn=0; cn<16; cn++){
    int bf = cn & 1;
    float4 vn;
    if (cn+1 < 16) vn = fetch(cn+1);
    #pragma unroll
    for (int k8=0; k8<16; k8+=8){
      int ac = k8 + (lane&3);
      #pragma unroll
      for (int jw=0; jw<NJ; jw++){
        int job = warp + jw*32;
        int jm = job / JN, jn = job % JN;
        unsigned bh[2][2];
        #pragma unroll
        for (int ni=0; ni<2; ni++){
          int bc = jn*16 + ni*8 + (lane>>2);
          bh[ni][0]=sB[bf*16+ac][bc];
          bh[ni][1]=sB[bf*16+ac+4][bc];
        }
        int ar = jm*16 + (lane>>2);
        unsigned ah[4];
        ah[0]=sA[bf*16+ac][ar];   ah[1]=sA[bf*16+ac][ar+8];
        ah[2]=sA[bf*16+ac+4][ar]; ah[3]=sA[bf*16+ac+4][ar+8];
        #pragma unroll
        for (int ni=0; ni<2; ni++) mma8(c[jw][ni], ah, bh[ni]);
      }
    }
    if (cn+1 < 16) commit(vn, bf^1);
    __syncthreads();
  }

  #pragma unroll
  for (int jw=0; jw<NJ; jw++){
    int job = warp + jw*32;
    int jm = job / JN, jn = job % JN;
    #pragma unroll
    for (int ni=0; ni<2; ni++){
      #pragma unroll
      for (int e=0; e<4; e++){
        int r = (lane>>2) + ((e>=2) ? 8 : 0);
        int col = jn*16 + ni*8 + (lane&3)*2 + (e&1);
        size_t row = m0 + jm*16 + r;
        float v = c[jw][ni][e];
        size_t xrow = ((row>>10)*12 + t)*1024 + (row&1023);
        if (EPI==0){
          v += g_Gx[xrow*128 + col] + bias[col];
          float s = 1.f/(1.f+expf(-v));
          if (col < 64)
            __stcg(&g_prh[row*64 + col], s * __ldcg(&g_h[row*64 + col]));
          else
            __stcg(&g_u[row*64 + (col-64)], s);
        } else {
          v += g_Cx[xrow*64 + col] + bias[col];
          float cc = tanhf(v);
          float u = __ldcg(&g_u[row*64 + col]);
          float h = __ldcg(&g_h[row*64 + col]);
          __stcg(&g_h[row*64 + col], u*h + (1.f-u)*cc);
        }
      }
    }
  }
}

__global__ void __launch_bounds__(1024) k_loop(
    const float* __restrict__ Wg, const float* __restrict__ bg,
    const float* __restrict__ Wc, const float* __restrict__ bc,
    const float* __restrict__ Wo1, const float* __restrict__ bo1,
    const float* __restrict__ Wo2, const float* __restrict__ bo2,
    float* __restrict__ out){
  __shared__ __align__(16) char sm[33792];
  int g = blockIdx.x >> 3;
  for (int t=0; t<12; t++){
    cheb_phase(sm, 4, 5,6,7);
    gbar_g(g);
    mma_phase<128,0>(sm, 4,5,6,7, Wg, 64, bg, t);
    gbar_g(g);
    cheb_phase(sm, 8, 5,6,7);
    gbar_g(g);
    mma_phase<64,1>(sm, 8,5,6,7, Wc, 64, bc, t);
    gbar_g(g);
  }
  // per-group output head: block handles rows m0..m0+127 (it wrote their h)
  int m0 = blockIdx.x*128;
  int warp = threadIdx.x>>5, lane = threadIdx.x&31;
  #pragma unroll
  for (int i=0;i<4;i++){
    int row = m0 + warp*4 + i;
    float h0 = __ldcg(&g_h[(size_t)row*64 + lane]);
    float h1 = __ldcg(&g_h[(size_t)row*64 + 32 + lane]);
    float a0 = bo1[lane], a1 = bo1[lane+32];
    #pragma unroll 16
    for (int k=0;k<64;k++){
      float hk = (k<32) ? __shfl_sync(0xffffffffu, h0, k)
                        : __shfl_sync(0xffffffffu, h1, k-32);
      a0 = fmaf(hk, Wo1[k*64 + lane],      a0);
      a1 = fmaf(hk, Wo1[k*64 + lane + 32], a1);
    }
    a0 = fmaxf(a0, 0.f); a1 = fmaxf(a1, 0.f);
    float p[12];
    #pragma unroll
    for (int q=0;q<12;q++)
      p[q] = a0*Wo2[lane*12 + q] + a1*Wo2[(lane+32)*12 + q];
    #pragma unroll
    for (int o=16;o;o>>=1)
      #pragma unroll
      for (int q=0;q<12;q++) p[q] += __shfl_xor_sync(0xffffffffu, p[q], o);
    if (lane < 12){
      int b = row>>10, n = row&1023;
      out[(size_t)(b*12 + lane)*1024 + n] = p[lane] + bo2[lane];
    }
  }
}

// ---------------- host launcher --------------------------------------------
extern "C" void kernel_launch(void* const* d_in, const int* in_sizes, int n_in,
                              void* d_out, int out_size){
  const float* X     = (const float*)d_in[0];
  const float* ZC    = (const float*)d_in[1];
  const int*   TE    = (const int*)  d_in[2];
  const float* Ls    = (const float*)d_in[3];
  const float* SE    = (const float*)d_in[4];
  const float* Wse1  = (const float*)d_in[5];
  const float* bse1  = (const float*)d_in[6];
  const float* Wse2  = (const float*)d_in[7];
  const float* bse2  = (const float*)d_in[8];
  const float* Wte1  = (const float*)d_in[9];
  const float* bte1  = (const float*)d_in[10];
  const float* Wte2  = (const float*)d_in[11];
  const float* bte2  = (const float*)d_in[12];
  const float* Win1  = (const float*)d_in[13];
  const float* bin1  = (const float*)d_in[14];
  const float* Win2  = (const float*)d_in[15];
  const float* bin2  = (const float*)d_in[16];
  const float* Wconv = (const float*)d_in[17];
  const float* bconv = (const float*)d_in[18];
  const float* Wg    = (const float*)d_in[19];
  const float* bg    = (const float*)d_in[20];
  const float* Wc    = (const float*)d_in[21];
  const float* bc    = (const float*)d_in[22];
  const float* Wo1   = (const float*)d_in[23];
  const float* bo1   = (const float*)d_in[24];
  const float* Wo2   = (const float*)d_in[25];
  const float* bo2   = (const float*)d_in[26];
  float* out = (float*)d_out;

  k_pre<<<512,256>>>(SE,Wse1,bse1,Wse2,bse2,Wte1,bte1,Wte2,bte2,TE,Ls);
  k_embed<<<6144,256>>>(X,ZC,Wconv,bconv,Win1,bin1,Win2,bin2);

  // precompute: x Chebyshev terms + combined x-part GEMM (Gx | Cx)
  k_cheb3<<<192*8,1024>>>(0, 1,2,3);
  k_mma<192,2><<<1536,384>>>(0,1,2,3, Wg, Wc, 0, Wg, 0);

  // persistent 12-step DCGRU loop + fused per-group output head
  k_loop<<<NBLK,1024>>>(Wg, bg, Wc, bc, Wo1, bo1, Wo2, bo2, out);
}